// round 6
// baseline (speedup 1.0000x reference)
#include <cuda_runtime.h>

// ---------------------------------------------------------------------------
// Problem constants
// ---------------------------------------------------------------------------
#define D_IN   120000
#define BATCH  512
#define H1     600
#define H2     300
#define H3     200

// Layer-1 nnz are counting-sorted by key = row * NB1 + (col >> CB_SHIFT)
// (row-major, 512-column blocks) so all 600 row-CTAs sweep xT in lockstep
// and the L2 working set is a narrow band.
#define CB_SHIFT 9
#define NB1      235           // ceil(120000 / 512)

// Bin layout (concatenated across layers so one global exclusive scan gives
// final positions into the shared pairs buffer directly):
#define BASE1 0
#define BINS1 (H1 * NB1)       // 141000
#define BASE2 (BASE1 + BINS1)  // 141000
#define BASE3 (BASE2 + H1)     // 141600
#define BASE4 (BASE3 + H2)     // 141900
#define BASE5 (BASE4 + H3)     // 142100
#define BINS_TOTAL (BASE5 + H3) // 142300

#define MAX_PAIRS 7300000      // total nnz = 7,264,000

// ---------------------------------------------------------------------------
// Static device scratch (allocation-free rule: __device__ globals)
// ---------------------------------------------------------------------------
__device__ float  g_xT[(size_t)D_IN * BATCH];   // 245.76 MB, x transposed [D][B]
__device__ float2 g_pairs[MAX_PAIRS];           // (col bits, val) sorted by bin
__device__ int    g_binCnt[BINS_TOTAL + 1];
__device__ int    g_binPtr[BINS_TOTAL + 1];
__device__ int    g_binFill[BINS_TOTAL + 1];
__device__ float  g_h1[H1 * BATCH];
__device__ float  g_h2[H1 * BATCH];
__device__ float  g_h3[H2 * BATCH];
__device__ float  g_h4[H3 * BATCH];

// ---------------------------------------------------------------------------
// 0) zero bin counters
// ---------------------------------------------------------------------------
__global__ void zero_bins_kernel() {
    int i = blockIdx.x * blockDim.x + threadIdx.x;
    if (i <= BINS_TOTAL) { g_binCnt[i] = 0; g_binFill[i] = 0; }
}

// ---------------------------------------------------------------------------
// 1) transpose x [B][D] -> g_xT [D][B]   (32x32 shared tile, coalesced both sides)
// ---------------------------------------------------------------------------
__global__ void transpose_x_kernel(const float* __restrict__ x) {
    __shared__ float tile[32][33];
    int c0 = blockIdx.x * 32;
    int b0 = blockIdx.y * 32;
    int tx = threadIdx.x, ty = threadIdx.y;
#pragma unroll
    for (int i = 0; i < 32; i += 8)
        tile[ty + i][tx] = x[(size_t)(b0 + ty + i) * D_IN + (c0 + tx)];
    __syncthreads();
#pragma unroll
    for (int i = 0; i < 32; i += 8)
        g_xT[(size_t)(c0 + ty + i) * BATCH + (b0 + tx)] = tile[tx][ty + i];
}

// ---------------------------------------------------------------------------
// 2) histogram nnz into bins.  key = row*nb + (col>>shift); shift=31 -> key=row
// ---------------------------------------------------------------------------
__global__ void hist_kernel(const int* __restrict__ idx, int nnz,
                            int base, int nb, int shift) {
    int j = blockIdx.x * blockDim.x + threadIdx.x;
    if (j >= nnz) return;
    int r = idx[j];
    int c = idx[nnz + j];
    int key = r * nb + (c >> shift);
    atomicAdd(&g_binCnt[base + key], 1);
}

// ---------------------------------------------------------------------------
// 3) exclusive scan over all BINS_TOTAL counters (single CTA, 1024 threads)
// ---------------------------------------------------------------------------
__global__ void scan_kernel() {
    __shared__ int wsum[32];
    __shared__ int s_carry;
    int tid = threadIdx.x, lane = tid & 31, wid = tid >> 5;
    if (tid == 0) s_carry = 0;
    __syncthreads();
    const int N = BINS_TOTAL;
    for (int base = 0; base < N; base += 1024) {
        int i = base + tid;
        int v0 = (i < N) ? g_binCnt[i] : 0;
        int v = v0;
#pragma unroll
        for (int d = 1; d < 32; d <<= 1) {
            int t = __shfl_up_sync(0xFFFFFFFFu, v, d);
            if (lane >= d) v += t;
        }
        if (lane == 31) wsum[wid] = v;
        __syncthreads();
        if (wid == 0) {
            int w = wsum[lane];
#pragma unroll
            for (int d = 1; d < 32; d <<= 1) {
                int t = __shfl_up_sync(0xFFFFFFFFu, w, d);
                if (lane >= d) w += t;
            }
            wsum[lane] = w;
        }
        __syncthreads();
        int carry = s_carry;
        int pre = (wid > 0) ? wsum[wid - 1] : 0;
        if (i < N) g_binPtr[i] = carry + pre + (v - v0);
        int chunk_total = wsum[31];
        __syncthreads();
        if (tid == 0) s_carry = carry + chunk_total;
        __syncthreads();
    }
    if (tid == 0) g_binPtr[N] = s_carry;
}

// ---------------------------------------------------------------------------
// 4) scatter (col, val) pairs to their sorted positions
// ---------------------------------------------------------------------------
__global__ void scatter_kernel(const int* __restrict__ idx,
                               const float* __restrict__ val, int nnz,
                               int base, int nb, int shift) {
    int j = blockIdx.x * blockDim.x + threadIdx.x;
    if (j >= nnz) return;
    int r = idx[j];
    int c = idx[nnz + j];
    int key = base + r * nb + (c >> shift);
    int pos = g_binPtr[key] + atomicAdd(&g_binFill[key], 1);
    g_pairs[pos] = make_float2(__int_as_float(c), val[j]);
}

// ---------------------------------------------------------------------------
// 5) SpMM: one CTA per output row, 512 threads = batch lanes.
//    Fused bias (+BN over batch via block reduce) (+SiLU).
//    mode: 0 = raw, 1 = silu, 2 = bn + silu
// ---------------------------------------------------------------------------
__global__ void __launch_bounds__(512) spmm_kernel(
    const float* __restrict__ inT,      // [in_d][512]
    const float* __restrict__ bias,
    const float* __restrict__ gamma,
    const float* __restrict__ beta,
    float* __restrict__ out,
    int base, int nb, int mode, int outDim, int outTransposed)
{
    __shared__ float2 sh[1024];
    int r = blockIdx.x;
    int tid = threadIdx.x;
    int start = g_binPtr[base + r * nb];
    int end   = g_binPtr[base + (r + 1) * nb];

    float acc = 0.0f;
    for (int b0 = start; b0 < end; b0 += 1024) {
        int n = min(1024, end - b0);
        __syncthreads();
        if (tid < n)       sh[tid]       = g_pairs[b0 + tid];
        if (tid + 512 < n) sh[tid + 512] = g_pairs[b0 + tid + 512];
        __syncthreads();
        int k = 0;
        for (; k + 4 <= n; k += 4) {
            float2 p0 = sh[k], p1 = sh[k + 1], p2 = sh[k + 2], p3 = sh[k + 3];
            float x0 = inT[__float_as_int(p0.x) * BATCH + tid];
            float x1 = inT[__float_as_int(p1.x) * BATCH + tid];
            float x2 = inT[__float_as_int(p2.x) * BATCH + tid];
            float x3 = inT[__float_as_int(p3.x) * BATCH + tid];
            acc += p0.y * x0;
            acc += p1.y * x1;
            acc += p2.y * x2;
            acc += p3.y * x3;
        }
        for (; k < n; k++) {
            float2 p = sh[k];
            acc += p.y * inT[__float_as_int(p.x) * BATCH + tid];
        }
    }
    acc += bias[r];

    float z = acc;
    if (mode >= 2) {
        // BatchNorm over the batch dimension (= this CTA's 512 threads)
        __shared__ float rsum[16], rsum2[16], bcast[2];
        float s = acc, s2 = acc * acc;
#pragma unroll
        for (int d = 16; d; d >>= 1) {
            s  += __shfl_xor_sync(0xFFFFFFFFu, s, d);
            s2 += __shfl_xor_sync(0xFFFFFFFFu, s2, d);
        }
        int lane = tid & 31, wid = tid >> 5;
        if (lane == 0) { rsum[wid] = s; rsum2[wid] = s2; }
        __syncthreads();
        if (wid == 0) {
            float a  = (lane < 16) ? rsum[lane]  : 0.0f;
            float a2 = (lane < 16) ? rsum2[lane] : 0.0f;
#pragma unroll
            for (int d = 8; d; d >>= 1) {
                a  += __shfl_xor_sync(0xFFFFFFFFu, a, d);
                a2 += __shfl_xor_sync(0xFFFFFFFFu, a2, d);
            }
            if (lane == 0) { bcast[0] = a; bcast[1] = a2; }
        }
        __syncthreads();
        float m   = bcast[0] * (1.0f / 512.0f);
        float var = bcast[1] * (1.0f / 512.0f) - m * m;
        z = (acc - m) * rsqrtf(var + 1e-5f) * gamma[r] + beta[r];
    }
    if (mode >= 1) {
        z = z * (1.0f / (1.0f + __expf(-z)));   // silu
    }
    if (outTransposed) out[r * BATCH + tid] = z;
    else               out[(size_t)tid * outDim + r] = z;
}

// ---------------------------------------------------------------------------
// kernel_launch: full pipeline, graph-capturable (kernel launches only)
// ---------------------------------------------------------------------------
extern "C" void kernel_launch(void* const* d_in, const int* in_sizes, int n_in,
                              void* d_out, int out_size) {
    const float* x    = (const float*)d_in[0];
    const int*   idx1 = (const int*)  d_in[1];
    const float* val1 = (const float*)d_in[2];
    const float* b1   = (const float*)d_in[3];
    const int*   idx2 = (const int*)  d_in[4];
    const float* val2 = (const float*)d_in[5];
    const float* b2   = (const float*)d_in[6];
    const int*   idx3 = (const int*)  d_in[7];
    const float* val3 = (const float*)d_in[8];
    const float* b3   = (const float*)d_in[9];
    const int*   idx4 = (const int*)  d_in[10];
    const float* val4 = (const float*)d_in[11];
    const float* b4   = (const float*)d_in[12];
    const int*   idx5 = (const int*)  d_in[13];
    const float* val5 = (const float*)d_in[14];
    const float* b5   = (const float*)d_in[15];
    const float* g1   = (const float*)d_in[16];
    const float* be1  = (const float*)d_in[17];
    const float* g2   = (const float*)d_in[18];
    const float* be2  = (const float*)d_in[19];
    const float* g3   = (const float*)d_in[20];
    const float* be3  = (const float*)d_in[21];

    int nnz1 = in_sizes[1]  / 2;
    int nnz2 = in_sizes[4]  / 2;
    int nnz3 = in_sizes[7]  / 2;
    int nnz4 = in_sizes[10] / 2;
    int nnz5 = in_sizes[13] / 2;

    float *xT, *h1, *h2, *h3, *h4;
    cudaGetSymbolAddress((void**)&xT, g_xT);
    cudaGetSymbolAddress((void**)&h1, g_h1);
    cudaGetSymbolAddress((void**)&h2, g_h2);
    cudaGetSymbolAddress((void**)&h3, g_h3);
    cudaGetSymbolAddress((void**)&h4, g_h4);

    // 0) zero counters
    zero_bins_kernel<<<(BINS_TOTAL + 256) / 256, 256>>>();

    // 1) transpose x -> xT
    transpose_x_kernel<<<dim3(D_IN / 32, BATCH / 32), dim3(32, 8)>>>(x);

    // 2) histograms (layer 1 keyed by (row, col-block); others by row only)
    hist_kernel<<<(nnz1 + 255) / 256, 256>>>(idx1, nnz1, BASE1, NB1, CB_SHIFT);
    hist_kernel<<<(nnz2 + 255) / 256, 256>>>(idx2, nnz2, BASE2, 1, 31);
    hist_kernel<<<(nnz3 + 255) / 256, 256>>>(idx3, nnz3, BASE3, 1, 31);
    hist_kernel<<<(nnz4 + 255) / 256, 256>>>(idx4, nnz4, BASE4, 1, 31);
    hist_kernel<<<(nnz5 + 255) / 256, 256>>>(idx5, nnz5, BASE5, 1, 31);

    // 3) global exclusive scan -> positions into g_pairs
    scan_kernel<<<1, 1024>>>();

    // 4) scatter (col,val) pairs
    scatter_kernel<<<(nnz1 + 255) / 256, 256>>>(idx1, val1, nnz1, BASE1, NB1, CB_SHIFT);
    scatter_kernel<<<(nnz2 + 255) / 256, 256>>>(idx2, val2, nnz2, BASE2, 1, 31);
    scatter_kernel<<<(nnz3 + 255) / 256, 256>>>(idx3, val3, nnz3, BASE3, 1, 31);
    scatter_kernel<<<(nnz4 + 255) / 256, 256>>>(idx4, val4, nnz4, BASE4, 1, 31);
    scatter_kernel<<<(nnz5 + 255) / 256, 256>>>(idx5, val5, nnz5, BASE5, 1, 31);

    // 5) the five fused sparse-linear layers
    //    L1: spLinear + BN(g1) + silu     (dominant: 7.2M nnz)
    spmm_kernel<<<H1, 512>>>(xT, b1, g1, be1, h1, BASE1, NB1, 2, H1, 1);
    //    L2: spLinear + silu
    spmm_kernel<<<H1, 512>>>(h1, b2, (const float*)0, (const float*)0, h2, BASE2, 1, 1, H1, 1);
    //    L3: spLinear + BN(g2) + silu
    spmm_kernel<<<H2, 512>>>(h2, b3, g2, be2, h3, BASE3, 1, 2, H2, 1);
    //    L4: spLinear + BN(g3) + silu
    spmm_kernel<<<H3, 512>>>(h3, b4, g3, be3, h4, BASE4, 1, 2, H3, 1);
    //    L5: spLinear, write row-major [B, H3] to d_out
    spmm_kernel<<<H3, 512>>>(h4, b5, (const float*)0, (const float*)0,
                             (float*)d_out, BASE5, 1, 0, H3, 0);
}

// round 8
// speedup vs baseline: 1.1567x; 1.1567x over previous
#include <cuda_runtime.h>
#include <cstdint>

// ---------------------------------------------------------------------------
// Problem constants
// ---------------------------------------------------------------------------
#define D_IN   120000
#define BATCH  512
#define H1     600
#define H2     300
#define H3     200

// ---------------------------------------------------------------------------
// Layer-1 SMEM-tiled SpMM geometry
// ---------------------------------------------------------------------------
#define COLB   384                  // columns per block (x tile 384x128 fp32 = 196.6KB)
#define NCB    313                  // ceil(120000/384); last block has 192 cols
#define BB     128                  // batch lanes per CTA
#define NBB    (BATCH / BB)         // 4
#define SPMM1_SMEM (COLB * 128 * 4) // 196608 B

// Bin layout: layer-1 bins keyed (colblock, row); small layers keyed (row)
#define BINS1  (NCB * H1)           // 187800
#define BASE2  BINS1
#define BASE3  (BASE2 + H1)
#define BASE4  (BASE3 + H2)
#define BASE5  (BASE4 + H3)
#define BINS_TOTAL (BASE5 + H3)     // 189100

#define MAX_PAIRS 7300000           // total nnz all layers = 7,264,000

// ---------------------------------------------------------------------------
// Static device scratch (allocation-free rule)
// ---------------------------------------------------------------------------
__device__ float2 g_pairs[MAX_PAIRS];                 // 58.4 MB
__device__ int    g_binCnt[BINS_TOTAL + 1];
__device__ int    g_binPtr[BINS_TOTAL + 1];
__device__ int    g_binFill[BINS_TOTAL + 1];
__device__ float  g_part[(size_t)NCB * H1 * BATCH];   // 384.6 MB partials [cb][r][b]
__device__ float  g_h1[H1 * BATCH];
__device__ float  g_h2[H1 * BATCH];
__device__ float  g_h3[H2 * BATCH];
__device__ float  g_h4[H3 * BATCH];

// ---------------------------------------------------------------------------
// 0) zero bin counters
// ---------------------------------------------------------------------------
__global__ void zero_bins_kernel() {
    int i = blockIdx.x * blockDim.x + threadIdx.x;
    if (i <= BINS_TOTAL) { g_binCnt[i] = 0; g_binFill[i] = 0; }
}

// ---------------------------------------------------------------------------
// 1) histograms
// ---------------------------------------------------------------------------
__global__ void hist1_kernel(const int* __restrict__ idx, int nnz) {
    int j = blockIdx.x * blockDim.x + threadIdx.x;
    if (j >= nnz) return;
    int r = idx[j];
    int c = idx[nnz + j];
    atomicAdd(&g_binCnt[(c / COLB) * H1 + r], 1);
}

__global__ void hist_kernel(const int* __restrict__ idx, int nnz, int base) {
    int j = blockIdx.x * blockDim.x + threadIdx.x;
    if (j >= nnz) return;
    atomicAdd(&g_binCnt[base + idx[j]], 1);
}

// ---------------------------------------------------------------------------
// 2) exclusive scan over all bins (single CTA, 1024 threads)
// ---------------------------------------------------------------------------
__global__ void scan_kernel() {
    __shared__ int wsum[32];
    __shared__ int s_carry;
    int tid = threadIdx.x, lane = tid & 31, wid = tid >> 5;
    if (tid == 0) s_carry = 0;
    __syncthreads();
    const int N = BINS_TOTAL;
    for (int base = 0; base < N; base += 1024) {
        int i = base + tid;
        int v0 = (i < N) ? g_binCnt[i] : 0;
        int v = v0;
#pragma unroll
        for (int d = 1; d < 32; d <<= 1) {
            int t = __shfl_up_sync(0xFFFFFFFFu, v, d);
            if (lane >= d) v += t;
        }
        if (lane == 31) wsum[wid] = v;
        __syncthreads();
        if (wid == 0) {
            int w = wsum[lane];
#pragma unroll
            for (int d = 1; d < 32; d <<= 1) {
                int t = __shfl_up_sync(0xFFFFFFFFu, w, d);
                if (lane >= d) w += t;
            }
            wsum[lane] = w;
        }
        __syncthreads();
        int carry = s_carry;
        int pre = (wid > 0) ? wsum[wid - 1] : 0;
        if (i < N) g_binPtr[i] = carry + pre + (v - v0);
        int chunk_total = wsum[31];
        __syncthreads();
        if (tid == 0) s_carry = carry + chunk_total;
        __syncthreads();
    }
    if (tid == 0) g_binPtr[N] = s_carry;
}

// ---------------------------------------------------------------------------
// 3) scatter pairs.  Layer 1: pairs.x = precomputed swizzled word offset:
//    word(cl, b) = cl*128 + (b ^ ((cl & 31) << 2))  -> store cl*128 + ((cl&31)<<2)
//    (the per-thread batch part is XORed in at use time: one LOP per pair)
// ---------------------------------------------------------------------------
__global__ void scatter1_kernel(const int* __restrict__ idx,
                                const float* __restrict__ val, int nnz) {
    int j = blockIdx.x * blockDim.x + threadIdx.x;
    if (j >= nnz) return;
    int r = idx[j];
    int c = idx[nnz + j];
    int cb = c / COLB;
    int cl = c - cb * COLB;
    int key = cb * H1 + r;
    int pos = g_binPtr[key] + atomicAdd(&g_binFill[key], 1);
    int px = cl * 128 + ((cl & 31) << 2);
    g_pairs[pos] = make_float2(__int_as_float(px), val[j]);
}

__global__ void scatter_kernel(const int* __restrict__ idx,
                               const float* __restrict__ val, int nnz, int base) {
    int j = blockIdx.x * blockDim.x + threadIdx.x;
    if (j >= nnz) return;
    int key = base + idx[j];
    int pos = g_binPtr[key] + atomicAdd(&g_binFill[key], 1);
    g_pairs[pos] = make_float2(__int_as_float(idx[nnz + j]), val[j]);
}

// ---------------------------------------------------------------------------
// 4) Layer-1 SpMM: CTA = (col-block, batch-block). x tile staged in SMEM with
//    an XOR swizzle so the 4-lane gather is one conflict-free LDS.128.
//    16 warps sweep the 600 rows (warp w: rows w, w+16, ...); each thread owns
//    4 consecutive batch lanes; partial row results -> g_part[cb][r][b].
// ---------------------------------------------------------------------------
__global__ void __launch_bounds__(512, 1) spmm1_kernel(const float* __restrict__ x) {
    extern __shared__ float xs[];
    const int cb = blockIdx.x;
    const int bbk = blockIdx.y;
    const int c0 = cb * COLB;
    const int ncols = min(COLB, D_IN - c0);
    const int tid = threadIdx.x;

    // ---- load x tile [ncols][128] with swizzle; global reads coalesced ----
    {
        const float* xb = x + (size_t)(bbk * BB) * D_IN + c0;
        const int nq = ncols >> 2;              // float4 per batch row
        const int total = nq * BB;
        for (int idx = tid; idx < total; idx += 512) {
            int cq = idx % nq;                  // consecutive across lanes
            int b  = idx / nq;
            float4 f = *(const float4*)(xb + (size_t)b * D_IN + 4 * cq);
            int cl = 4 * cq;
#pragma unroll
            for (int j = 0; j < 4; ++j) {
                int clj = cl + j;
                xs[clj * 128 + (b ^ ((clj & 31) << 2))] = (&f.x)[j];
            }
        }
    }
    __syncthreads();

    const int w    = tid >> 5;        // warp 0..15: rows w, w+16, ...
    const int lane = tid & 31;        // batch quad: lanes 4*lane .. 4*lane+3
    const uint32_t l4 = (uint32_t)lane << 2;

    for (int r = w; r < H1; r += 16) {
        const int key = cb * H1 + r;
        int s = g_binPtr[key];
        const int e = g_binPtr[key + 1];
        float4 acc = make_float4(0.f, 0.f, 0.f, 0.f);

        for (; s + 2 <= e; s += 2) {
            float2 p0 = __ldg(&g_pairs[s]);
            float2 p1 = __ldg(&g_pairs[s + 1]);
            uint32_t o0 = __float_as_uint(p0.x) ^ l4;
            uint32_t o1 = __float_as_uint(p1.x) ^ l4;
            float4 v0 = *(const float4*)(xs + o0);
            float4 v1 = *(const float4*)(xs + o1);
            acc.x += p0.y * v0.x;  acc.y += p0.y * v0.y;
            acc.z += p0.y * v0.z;  acc.w += p0.y * v0.w;
            acc.x += p1.y * v1.x;  acc.y += p1.y * v1.y;
            acc.z += p1.y * v1.z;  acc.w += p1.y * v1.w;
        }
        if (s < e) {
            float2 p = __ldg(&g_pairs[s]);
            uint32_t o = __float_as_uint(p.x) ^ l4;
            float4 v = *(const float4*)(xs + o);
            acc.x += p.y * v.x;  acc.y += p.y * v.y;
            acc.z += p.y * v.z;  acc.w += p.y * v.w;
        }
        // flush partial: g_part[(cb*600 + r)*512 + bbk*128 + 4*lane .. +3]
        float* dst = g_part + ((size_t)key) * BATCH + bbk * BB + 4 * lane;
        *(float4*)dst = acc;
    }
}

// ---------------------------------------------------------------------------
// 5) reduce K-split partials + bias + BN + SiLU -> g_h1 [r][512]
// ---------------------------------------------------------------------------
__global__ void __launch_bounds__(512) bn_silu_kernel(
    const float* __restrict__ bias, const float* __restrict__ gamma,
    const float* __restrict__ beta, float* __restrict__ out)
{
    int r = blockIdx.x, tid = threadIdx.x;
    const float* p = g_part + (size_t)r * BATCH + tid;
    const size_t stride = (size_t)H1 * BATCH;
    float a0 = 0.f, a1 = 0.f, a2 = 0.f, a3 = 0.f;
    int cbi = 0;
    for (; cbi + 4 <= NCB; cbi += 4) {
        a0 += p[(size_t)(cbi + 0) * stride];
        a1 += p[(size_t)(cbi + 1) * stride];
        a2 += p[(size_t)(cbi + 2) * stride];
        a3 += p[(size_t)(cbi + 3) * stride];
    }
    for (; cbi < NCB; ++cbi) a0 += p[(size_t)cbi * stride];
    float acc = (a0 + a1) + (a2 + a3) + bias[r];

    __shared__ float rsum[16], rsum2[16], bcast[2];
    float s = acc, s2 = acc * acc;
#pragma unroll
    for (int d = 16; d; d >>= 1) {
        s  += __shfl_xor_sync(0xFFFFFFFFu, s, d);
        s2 += __shfl_xor_sync(0xFFFFFFFFu, s2, d);
    }
    int lane = tid & 31, wid = tid >> 5;
    if (lane == 0) { rsum[wid] = s; rsum2[wid] = s2; }
    __syncthreads();
    if (wid == 0) {
        float a  = (lane < 16) ? rsum[lane]  : 0.0f;
        float a2w = (lane < 16) ? rsum2[lane] : 0.0f;
#pragma unroll
        for (int d = 8; d; d >>= 1) {
            a   += __shfl_xor_sync(0xFFFFFFFFu, a, d);
            a2w += __shfl_xor_sync(0xFFFFFFFFu, a2w, d);
        }
        if (lane == 0) { bcast[0] = a; bcast[1] = a2w; }
    }
    __syncthreads();
    float m   = bcast[0] * (1.0f / 512.0f);
    float var = bcast[1] * (1.0f / 512.0f) - m * m;
    float z = (acc - m) * rsqrtf(var + 1e-5f) * gamma[r] + beta[r];
    z = z * (1.0f / (1.0f + __expf(-z)));
    out[r * BATCH + tid] = z;
}

// ---------------------------------------------------------------------------
// 6) small sparse layers 2..5 (proven round-5 path; inputs tiny, L2-resident)
//    mode: 0 = raw, 1 = silu, 2 = bn + silu
// ---------------------------------------------------------------------------
__global__ void __launch_bounds__(512) spmm_kernel(
    const float* __restrict__ inT, const float* __restrict__ bias,
    const float* __restrict__ gamma, const float* __restrict__ beta,
    float* __restrict__ out, int base, int mode, int outDim, int outTransposed)
{
    __shared__ float2 sh[1024];
    int r = blockIdx.x, tid = threadIdx.x;
    int start = g_binPtr[base + r];
    int end   = g_binPtr[base + r + 1];

    float acc = 0.0f;
    for (int b0 = start; b0 < end; b0 += 1024) {
        int n = min(1024, end - b0);
        __syncthreads();
        if (tid < n)       sh[tid]       = g_pairs[b0 + tid];
        if (tid + 512 < n) sh[tid + 512] = g_pairs[b0 + tid + 512];
        __syncthreads();
        int k = 0;
        for (; k + 4 <= n; k += 4) {
            float2 p0 = sh[k], p1 = sh[k+1], p2 = sh[k+2], p3 = sh[k+3];
            acc += p0.y * inT[__float_as_int(p0.x) * BATCH + tid];
            acc += p1.y * inT[__float_as_int(p1.x) * BATCH + tid];
            acc += p2.y * inT[__float_as_int(p2.x) * BATCH + tid];
            acc += p3.y * inT[__float_as_int(p3.x) * BATCH + tid];
        }
        for (; k < n; k++) {
            float2 p = sh[k];
            acc += p.y * inT[__float_as_int(p.x) * BATCH + tid];
        }
    }
    acc += bias[r];

    float z = acc;
    if (mode >= 2) {
        __shared__ float rsum[16], rsum2[16], bcast[2];
        float s = acc, s2 = acc * acc;
#pragma unroll
        for (int d = 16; d; d >>= 1) {
            s  += __shfl_xor_sync(0xFFFFFFFFu, s, d);
            s2 += __shfl_xor_sync(0xFFFFFFFFu, s2, d);
        }
        int lane = tid & 31, wid = tid >> 5;
        if (lane == 0) { rsum[wid] = s; rsum2[wid] = s2; }
        __syncthreads();
        if (wid == 0) {
            float a  = (lane < 16) ? rsum[lane]  : 0.0f;
            float a2 = (lane < 16) ? rsum2[lane] : 0.0f;
#pragma unroll
            for (int d = 8; d; d >>= 1) {
                a  += __shfl_xor_sync(0xFFFFFFFFu, a, d);
                a2 += __shfl_xor_sync(0xFFFFFFFFu, a2, d);
            }
            if (lane == 0) { bcast[0] = a; bcast[1] = a2; }
        }
        __syncthreads();
        float m   = bcast[0] * (1.0f / 512.0f);
        float var = bcast[1] * (1.0f / 512.0f) - m * m;
        z = (acc - m) * rsqrtf(var + 1e-5f) * gamma[r] + beta[r];
    }
    if (mode >= 1) z = z * (1.0f / (1.0f + __expf(-z)));
    if (outTransposed) out[r * BATCH + tid] = z;
    else               out[(size_t)tid * outDim + r] = z;
}

// ---------------------------------------------------------------------------
// kernel_launch: kernel launches only (graph-capturable)
// ---------------------------------------------------------------------------
extern "C" void kernel_launch(void* const* d_in, const int* in_sizes, int n_in,
                              void* d_out, int out_size) {
    const float* x    = (const float*)d_in[0];
    const int*   idx1 = (const int*)  d_in[1];
    const float* val1 = (const float*)d_in[2];
    const float* b1   = (const float*)d_in[3];
    const int*   idx2 = (const int*)  d_in[4];
    const float* val2 = (const float*)d_in[5];
    const float* b2   = (const float*)d_in[6];
    const int*   idx3 = (const int*)  d_in[7];
    const float* val3 = (const float*)d_in[8];
    const float* b3   = (const float*)d_in[9];
    const int*   idx4 = (const int*)  d_in[10];
    const float* val4 = (const float*)d_in[11];
    const float* b4   = (const float*)d_in[12];
    const int*   idx5 = (const int*)  d_in[13];
    const float* val5 = (const float*)d_in[14];
    const float* b5   = (const float*)d_in[15];
    const float* g1   = (const float*)d_in[16];
    const float* be1  = (const float*)d_in[17];
    const float* g2   = (const float*)d_in[18];
    const float* be2  = (const float*)d_in[19];
    const float* g3   = (const float*)d_in[20];
    const float* be3  = (const float*)d_in[21];

    int nnz1 = in_sizes[1]  / 2;
    int nnz2 = in_sizes[4]  / 2;
    int nnz3 = in_sizes[7]  / 2;
    int nnz4 = in_sizes[10] / 2;
    int nnz5 = in_sizes[13] / 2;

    float *h1, *h2, *h3, *h4;
    cudaGetSymbolAddress((void**)&h1, g_h1);
    cudaGetSymbolAddress((void**)&h2, g_h2);
    cudaGetSymbolAddress((void**)&h3, g_h3);
    cudaGetSymbolAddress((void**)&h4, g_h4);

    cudaFuncSetAttribute(spmm1_kernel,
                         cudaFuncAttributeMaxDynamicSharedMemorySize, SPMM1_SMEM);

    // 0) zero counters
    zero_bins_kernel<<<(BINS_TOTAL + 256) / 256, 256>>>();

    // 1) histograms
    hist1_kernel<<<(nnz1 + 255) / 256, 256>>>(idx1, nnz1);
    hist_kernel<<<(nnz2 + 255) / 256, 256>>>(idx2, nnz2, BASE2);
    hist_kernel<<<(nnz3 + 255) / 256, 256>>>(idx3, nnz3, BASE3);
    hist_kernel<<<(nnz4 + 255) / 256, 256>>>(idx4, nnz4, BASE4);
    hist_kernel<<<(nnz5 + 255) / 256, 256>>>(idx5, nnz5, BASE5);

    // 2) global exclusive scan
    scan_kernel<<<1, 1024>>>();

    // 3) scatter pairs (layer 1 stores precomputed swizzled offsets)
    scatter1_kernel<<<(nnz1 + 255) / 256, 256>>>(idx1, val1, nnz1);
    scatter_kernel<<<(nnz2 + 255) / 256, 256>>>(idx2, val2, nnz2, BASE2);
    scatter_kernel<<<(nnz3 + 255) / 256, 256>>>(idx3, val3, nnz3, BASE3);
    scatter_kernel<<<(nnz4 + 255) / 256, 256>>>(idx4, val4, nnz4, BASE4);
    scatter_kernel<<<(nnz5 + 255) / 256, 256>>>(idx5, val5, nnz5, BASE5);

    // 4) layer 1: SMEM-tiled SpMM -> partials -> reduce + BN + SiLU
    spmm1_kernel<<<dim3(NCB, NBB), 512, SPMM1_SMEM>>>(x);
    bn_silu_kernel<<<H1, 512>>>(b1, g1, be1, h1);

    // 5) layers 2..5
    spmm_kernel<<<H1, 512>>>(h1, b2, (const float*)0, (const float*)0, h2, BASE2, 1, H1, 1);
    spmm_kernel<<<H2, 512>>>(h2, b3, g2, be2, h3, BASE3, 2, H2, 1);
    spmm_kernel<<<H3, 512>>>(h3, b4, g3, be3, h4, BASE4, 2, H3, 1);
    spmm_kernel<<<H3, 512>>>(h4, b5, (const float*)0, (const float*)0,
                             (float*)d_out, BASE5, 0, H3, 0);
}

// round 9
// speedup vs baseline: 1.3958x; 1.2067x over previous
#include <cuda_runtime.h>
#include <cstdint>

// ---------------------------------------------------------------------------
// Problem constants
// ---------------------------------------------------------------------------
#define D_IN   120000
#define BATCH  512
#define H1     600
#define H2     300
#define H3     200

// ---------------------------------------------------------------------------
// Layer-1 SMEM-tiled SpMM geometry
// ---------------------------------------------------------------------------
#define COLB   384                  // columns per block (x tile 384x128 fp32)
#define NCB    313                  // ceil(120000/384); last block has 192 cols
#define BB     128                  // batch lanes per CTA
#define NBB    (BATCH / BB)         // 4
#define XTILE_BYTES (COLB * 128 * 4)            // 196608
#define SPMM1_SMEM (XTILE_BYTES + (H1 + 1) * 4) // +binPtr cache = 199012 B

// Bin layout: layer-1 bins keyed (colblock, row); small layers keyed (row)
#define BINS1  (NCB * H1)           // 187800
#define BASE2  BINS1
#define BASE3  (BASE2 + H1)
#define BASE4  (BASE3 + H2)
#define BASE5  (BASE4 + H3)
#define BINS_TOTAL (BASE5 + H3)     // 189100

#define SCAN_CHUNK 4096
#define NCHUNK ((BINS_TOTAL + SCAN_CHUNK - 1) / SCAN_CHUNK)  // 47

#define MAX_PAIRS 7300000           // total nnz all layers = 7,264,000

// ---------------------------------------------------------------------------
// Static device scratch (allocation-free rule)
// ---------------------------------------------------------------------------
__device__ float2 g_pairs[MAX_PAIRS];                 // 58.4 MB
__device__ int    g_binCnt[BINS_TOTAL + 1];
__device__ int    g_binPtr[BINS_TOTAL + 1];
__device__ int    g_binFill[BINS_TOTAL + 1];
__device__ int    g_chunkSum[NCHUNK];
__device__ float  g_part[(size_t)NCB * H1 * BATCH];   // 384.6 MB partials [cb][r][b]
__device__ float  g_h1[H1 * BATCH];
__device__ float  g_h2[H1 * BATCH];
__device__ float  g_h3[H2 * BATCH];
__device__ float  g_h4[H3 * BATCH];

// ---------------------------------------------------------------------------
// 0) zero bin counters
// ---------------------------------------------------------------------------
__global__ void zero_bins_kernel() {
    int i = blockIdx.x * blockDim.x + threadIdx.x;
    if (i <= BINS_TOTAL) { g_binCnt[i] = 0; g_binFill[i] = 0; }
}

// ---------------------------------------------------------------------------
// 1) histograms: layer 1 keyed (colblock, row); layers 2..5 fused, keyed row
// ---------------------------------------------------------------------------
__global__ void hist1_kernel(const int* __restrict__ idx, int nnz) {
    int j = blockIdx.x * blockDim.x + threadIdx.x;
    if (j >= nnz) return;
    int r = idx[j];
    int c = idx[nnz + j];
    atomicAdd(&g_binCnt[(c / COLB) * H1 + r], 1);
}

__global__ void hist_small_kernel(
    const int* __restrict__ i2, int n2, const int* __restrict__ i3, int n3,
    const int* __restrict__ i4, int n4, const int* __restrict__ i5, int n5)
{
    const int* p; int n, base;
    switch (blockIdx.y) {
        case 0: p = i2; n = n2; base = BASE2; break;
        case 1: p = i3; n = n3; base = BASE3; break;
        case 2: p = i4; n = n4; base = BASE4; break;
        default: p = i5; n = n5; base = BASE5; break;
    }
    int j = blockIdx.x * blockDim.x + threadIdx.x;
    if (j < n) atomicAdd(&g_binCnt[base + p[j]], 1);
}

// ---------------------------------------------------------------------------
// 2) 3-phase exclusive scan over BINS_TOTAL counters
// ---------------------------------------------------------------------------
__global__ void __launch_bounds__(1024) scan1_kernel() {
    __shared__ int wsum[32];
    int chunk = blockIdx.x;
    int tid = threadIdx.x, lane = tid & 31, wid = tid >> 5;
    int i0 = chunk * SCAN_CHUNK + tid * 4;
    int v0 = (i0 + 0 < BINS_TOTAL) ? g_binCnt[i0 + 0] : 0;
    int v1 = (i0 + 1 < BINS_TOTAL) ? g_binCnt[i0 + 1] : 0;
    int v2 = (i0 + 2 < BINS_TOTAL) ? g_binCnt[i0 + 2] : 0;
    int v3 = (i0 + 3 < BINS_TOTAL) ? g_binCnt[i0 + 3] : 0;
    int local = v0 + v1 + v2 + v3;
    int inc = local;
#pragma unroll
    for (int d = 1; d < 32; d <<= 1) {
        int t = __shfl_up_sync(0xFFFFFFFFu, inc, d);
        if (lane >= d) inc += t;
    }
    if (lane == 31) wsum[wid] = inc;
    __syncthreads();
    if (wid == 0) {
        int w = wsum[lane];
#pragma unroll
        for (int d = 1; d < 32; d <<= 1) {
            int t = __shfl_up_sync(0xFFFFFFFFu, w, d);
            if (lane >= d) w += t;
        }
        wsum[lane] = w;
    }
    __syncthreads();
    int run = inc - local + (wid ? wsum[wid - 1] : 0);
    if (i0 + 0 < BINS_TOTAL) g_binPtr[i0 + 0] = run; run += v0;
    if (i0 + 1 < BINS_TOTAL) g_binPtr[i0 + 1] = run; run += v1;
    if (i0 + 2 < BINS_TOTAL) g_binPtr[i0 + 2] = run; run += v2;
    if (i0 + 3 < BINS_TOTAL) g_binPtr[i0 + 3] = run; run += v3;
    if (tid == 1023) g_chunkSum[chunk] = run;   // block total
}

__global__ void scan2_kernel() {
    if (threadIdx.x == 0) {
        int acc = 0;
#pragma unroll 1
        for (int i = 0; i < NCHUNK; ++i) {
            int t = g_chunkSum[i];
            g_chunkSum[i] = acc;
            acc += t;
        }
        g_binPtr[BINS_TOTAL] = acc;
    }
}

__global__ void scan3_kernel() {
    int i = blockIdx.x * 1024 + threadIdx.x;
    if (i < BINS_TOTAL) g_binPtr[i] += g_chunkSum[i / SCAN_CHUNK];
}

// ---------------------------------------------------------------------------
// 3) scatter pairs.  Layer 1 stores precomputed swizzled word offset:
//    word(cl, b) = cl*128 + (b ^ ((cl & 31) << 2))  -> store cl*128 + ((cl&31)<<2)
// ---------------------------------------------------------------------------
__global__ void scatter1_kernel(const int* __restrict__ idx,
                                const float* __restrict__ val, int nnz) {
    int j = blockIdx.x * blockDim.x + threadIdx.x;
    if (j >= nnz) return;
    int r = idx[j];
    int c = idx[nnz + j];
    int cb = c / COLB;
    int cl = c - cb * COLB;
    int key = cb * H1 + r;
    int pos = g_binPtr[key] + atomicAdd(&g_binFill[key], 1);
    int px = cl * 128 + ((cl & 31) << 2);
    g_pairs[pos] = make_float2(__int_as_float(px), val[j]);
}

__global__ void scatter_small_kernel(
    const int* __restrict__ i2, const float* __restrict__ v2, int n2,
    const int* __restrict__ i3, const float* __restrict__ v3, int n3,
    const int* __restrict__ i4, const float* __restrict__ v4, int n4,
    const int* __restrict__ i5, const float* __restrict__ v5, int n5)
{
    const int* p; const float* v; int n, base;
    switch (blockIdx.y) {
        case 0: p = i2; v = v2; n = n2; base = BASE2; break;
        case 1: p = i3; v = v3; n = n3; base = BASE3; break;
        case 2: p = i4; v = v4; n = n4; base = BASE4; break;
        default: p = i5; v = v5; n = n5; base = BASE5; break;
    }
    int j = blockIdx.x * blockDim.x + threadIdx.x;
    if (j >= n) return;
    int key = base + p[j];
    int pos = g_binPtr[key] + atomicAdd(&g_binFill[key], 1);
    g_pairs[pos] = make_float2(__int_as_float(p[n + j]), v[j]);
}

// ---------------------------------------------------------------------------
// 4) Layer-1 SpMM: CTA = (col-block, batch-block), 1024 threads = 32 warps.
//    x tile + binPtr range staged in SMEM; pairs streamed as float4 (2 pairs)
//    with 1-deep prefetch; warp w sweeps rows w, w+32, ...
// ---------------------------------------------------------------------------
__global__ void __launch_bounds__(1024, 1) spmm1_kernel(const float* __restrict__ x) {
    extern __shared__ char smem[];
    float* xs  = (float*)smem;
    int* sPtr  = (int*)(smem + XTILE_BYTES);
    const int cb  = blockIdx.x;
    const int bbk = blockIdx.y;
    const int c0 = cb * COLB;
    const int ncols = min(COLB, D_IN - c0);
    const int tid = threadIdx.x;

    // binPtr range for this colblock -> SMEM (601 ints)
    for (int i = tid; i <= H1; i += 1024)
        sPtr[i] = g_binPtr[cb * H1 + i];

    // x tile [ncols][128] with XOR swizzle; global reads coalesced float4
    {
        const float* xb = x + (size_t)(bbk * BB) * D_IN + c0;
        const int nq = ncols >> 2;
        const int total = nq * BB;
        for (int idx = tid; idx < total; idx += 1024) {
            int cq = idx % nq;
            int b  = idx / nq;
            float4 f = *(const float4*)(xb + (size_t)b * D_IN + 4 * cq);
            int cl = 4 * cq;
#pragma unroll
            for (int j = 0; j < 4; ++j) {
                int clj = cl + j;
                xs[clj * 128 + (b ^ ((clj & 31) << 2))] = (&f.x)[j];
            }
        }
    }
    __syncthreads();

    const int w    = tid >> 5;          // warp 0..31: rows w, w+32, ...
    const int lane = tid & 31;          // batch quad 4*lane .. 4*lane+3
    const uint32_t l4 = (uint32_t)lane << 2;

    for (int r = w; r < H1; r += 32) {
        int s = sPtr[r];
        const int e = sPtr[r + 1];
        float4 acc0 = make_float4(0.f, 0.f, 0.f, 0.f);
        float4 acc1 = make_float4(0.f, 0.f, 0.f, 0.f);

        if ((s & 1) && s < e) {          // peel to 16B alignment
            float2 p = __ldg(&g_pairs[s]); ++s;
            const float4 v = *(const float4*)(xs + (__float_as_uint(p.x) ^ l4));
            acc0.x += p.y * v.x; acc0.y += p.y * v.y;
            acc0.z += p.y * v.z; acc0.w += p.y * v.w;
        }
        const int n2 = (e - s) >> 1;
        const float4* pq = (const float4*)(g_pairs + s);
        if (n2 > 0) {
            float4 q = __ldg(&pq[0]);
            for (int i = 0; i < n2; ++i) {
                float4 qn = (i + 1 < n2) ? __ldg(&pq[i + 1]) : q;
                const float4 v0 = *(const float4*)(xs + (__float_as_uint(q.x) ^ l4));
                acc0.x += q.y * v0.x; acc0.y += q.y * v0.y;
                acc0.z += q.y * v0.z; acc0.w += q.y * v0.w;
                const float4 v1 = *(const float4*)(xs + (__float_as_uint(q.z) ^ l4));
                acc1.x += q.w * v1.x; acc1.y += q.w * v1.y;
                acc1.z += q.w * v1.z; acc1.w += q.w * v1.w;
                q = qn;
            }
        }
        if ((e - s) & 1) {               // tail pair
            float2 p = __ldg(&g_pairs[e - 1]);
            const float4 v = *(const float4*)(xs + (__float_as_uint(p.x) ^ l4));
            acc0.x += p.y * v.x; acc0.y += p.y * v.y;
            acc0.z += p.y * v.z; acc0.w += p.y * v.w;
        }
        float4 acc = make_float4(acc0.x + acc1.x, acc0.y + acc1.y,
                                 acc0.z + acc1.z, acc0.w + acc1.w);
        *(float4*)(g_part + (size_t)(cb * H1 + r) * BATCH + bbk * BB + 4 * lane) = acc;
    }
}

// ---------------------------------------------------------------------------
// 5) reduce colblock partials + bias + BN + SiLU -> g_h1 [r][512]
// ---------------------------------------------------------------------------
__global__ void __launch_bounds__(512) bn_silu_kernel(
    const float* __restrict__ bias, const float* __restrict__ gamma,
    const float* __restrict__ beta, float* __restrict__ out)
{
    int r = blockIdx.x, tid = threadIdx.x;
    const float* p = g_part + (size_t)r * BATCH + tid;
    const size_t stride = (size_t)H1 * BATCH;
    float a0 = 0.f, a1 = 0.f, a2 = 0.f, a3 = 0.f;
    int cbi = 0;
    for (; cbi + 4 <= NCB; cbi += 4) {
        a0 += p[(size_t)(cbi + 0) * stride];
        a1 += p[(size_t)(cbi + 1) * stride];
        a2 += p[(size_t)(cbi + 2) * stride];
        a3 += p[(size_t)(cbi + 3) * stride];
    }
    for (; cbi < NCB; ++cbi) a0 += p[(size_t)cbi * stride];
    float acc = (a0 + a1) + (a2 + a3) + bias[r];

    __shared__ float rsum[16], rsum2[16], bcast[2];
    float s = acc, s2 = acc * acc;
#pragma unroll
    for (int d = 16; d; d >>= 1) {
        s  += __shfl_xor_sync(0xFFFFFFFFu, s, d);
        s2 += __shfl_xor_sync(0xFFFFFFFFu, s2, d);
    }
    int lane = tid & 31, wid = tid >> 5;
    if (lane == 0) { rsum[wid] = s; rsum2[wid] = s2; }
    __syncthreads();
    if (wid == 0) {
        float a   = (lane < 16) ? rsum[lane]  : 0.0f;
        float a2w = (lane < 16) ? rsum2[lane] : 0.0f;
#pragma unroll
        for (int d = 8; d; d >>= 1) {
            a   += __shfl_xor_sync(0xFFFFFFFFu, a, d);
            a2w += __shfl_xor_sync(0xFFFFFFFFu, a2w, d);
        }
        if (lane == 0) { bcast[0] = a; bcast[1] = a2w; }
    }
    __syncthreads();
    float m   = bcast[0] * (1.0f / 512.0f);
    float var = bcast[1] * (1.0f / 512.0f) - m * m;
    float z = (acc - m) * rsqrtf(var + 1e-5f) * gamma[r] + beta[r];
    z = z * (1.0f / (1.0f + __expf(-z)));
    out[r * BATCH + tid] = z;
}

// ---------------------------------------------------------------------------
// 6) small sparse layers 2..5;  mode: 0 = raw, 1 = silu, 2 = bn + silu
// ---------------------------------------------------------------------------
__global__ void __launch_bounds__(512) spmm_kernel(
    const float* __restrict__ inT, const float* __restrict__ bias,
    const float* __restrict__ gamma, const float* __restrict__ beta,
    float* __restrict__ out, int base, int mode, int outDim, int outTransposed)
{
    __shared__ float2 sh[1024];
    int r = blockIdx.x, tid = threadIdx.x;
    int start = g_binPtr[base + r];
    int end   = g_binPtr[base + r + 1];

    float acc = 0.0f;
    for (int b0 = start; b0 < end; b0 += 1024) {
        int n = min(1024, end - b0);
        __syncthreads();
        if (tid < n)       sh[tid]       = g_pairs[b0 + tid];
        if (tid + 512 < n) sh[tid + 512] = g_pairs[b0 + tid + 512];
        __syncthreads();
        int k = 0;
        for (; k + 4 <= n; k += 4) {
            float2 p0 = sh[k], p1 = sh[k+1], p2 = sh[k+2], p3 = sh[k+3];
            acc += p0.y * inT[__float_as_int(p0.x) * BATCH + tid];
            acc += p1.y * inT[__float_as_int(p1.x) * BATCH + tid];
            acc += p2.y * inT[__float_as_int(p2.x) * BATCH + tid];
            acc += p3.y * inT[__float_as_int(p3.x) * BATCH + tid];
        }
        for (; k < n; k++) {
            float2 p = sh[k];
            acc += p.y * inT[__float_as_int(p.x) * BATCH + tid];
        }
    }
    acc += bias[r];

    float z = acc;
    if (mode >= 2) {
        __shared__ float rsum[16], rsum2[16], bcast[2];
        float s = acc, s2 = acc * acc;
#pragma unroll
        for (int d = 16; d; d >>= 1) {
            s  += __shfl_xor_sync(0xFFFFFFFFu, s, d);
            s2 += __shfl_xor_sync(0xFFFFFFFFu, s2, d);
        }
        int lane = tid & 31, wid = tid >> 5;
        if (lane == 0) { rsum[wid] = s; rsum2[wid] = s2; }
        __syncthreads();
        if (wid == 0) {
            float a  = (lane < 16) ? rsum[lane]  : 0.0f;
            float a2 = (lane < 16) ? rsum2[lane] : 0.0f;
#pragma unroll
            for (int d = 8; d; d >>= 1) {
                a  += __shfl_xor_sync(0xFFFFFFFFu, a, d);
                a2 += __shfl_xor_sync(0xFFFFFFFFu, a2, d);
            }
            if (lane == 0) { bcast[0] = a; bcast[1] = a2; }
        }
        __syncthreads();
        float m   = bcast[0] * (1.0f / 512.0f);
        float var = bcast[1] * (1.0f / 512.0f) - m * m;
        z = (acc - m) * rsqrtf(var + 1e-5f) * gamma[r] + beta[r];
    }
    if (mode >= 1) z = z * (1.0f / (1.0f + __expf(-z)));
    if (outTransposed) out[r * BATCH + tid] = z;
    else               out[(size_t)tid * outDim + r] = z;
}

// ---------------------------------------------------------------------------
// kernel_launch: kernel launches only (graph-capturable)
// ---------------------------------------------------------------------------
extern "C" void kernel_launch(void* const* d_in, const int* in_sizes, int n_in,
                              void* d_out, int out_size) {
    const float* x    = (const float*)d_in[0];
    const int*   idx1 = (const int*)  d_in[1];
    const float* val1 = (const float*)d_in[2];
    const float* b1   = (const float*)d_in[3];
    const int*   idx2 = (const int*)  d_in[4];
    const float* val2 = (const float*)d_in[5];
    const float* b2   = (const float*)d_in[6];
    const int*   idx3 = (const int*)  d_in[7];
    const float* val3 = (const float*)d_in[8];
    const float* b3   = (const float*)d_in[9];
    const int*   idx4 = (const int*)  d_in[10];
    const float* val4 = (const float*)d_in[11];
    const float* b4   = (const float*)d_in[12];
    const int*   idx5 = (const int*)  d_in[13];
    const float* val5 = (const float*)d_in[14];
    const float* b5   = (const float*)d_in[15];
    const float* g1   = (const float*)d_in[16];
    const float* be1  = (const float*)d_in[17];
    const float* g2   = (const float*)d_in[18];
    const float* be2  = (const float*)d_in[19];
    const float* g3   = (const float*)d_in[20];
    const float* be3  = (const float*)d_in[21];

    int nnz1 = in_sizes[1]  / 2;
    int nnz2 = in_sizes[4]  / 2;
    int nnz3 = in_sizes[7]  / 2;
    int nnz4 = in_sizes[10] / 2;
    int nnz5 = in_sizes[13] / 2;

    float *h1, *h2, *h3, *h4;
    cudaGetSymbolAddress((void**)&h1, g_h1);
    cudaGetSymbolAddress((void**)&h2, g_h2);
    cudaGetSymbolAddress((void**)&h3, g_h3);
    cudaGetSymbolAddress((void**)&h4, g_h4);

    cudaFuncSetAttribute(spmm1_kernel,
                         cudaFuncAttributeMaxDynamicSharedMemorySize, SPMM1_SMEM);

    // 0) zero counters
    zero_bins_kernel<<<(BINS_TOTAL + 256) / 256, 256>>>();

    // 1) histograms (layer 1 + fused small layers)
    hist1_kernel<<<(nnz1 + 255) / 256, 256>>>(idx1, nnz1);
    {
        int mx = max(max(nnz2, nnz3), max(nnz4, nnz5));
        hist_small_kernel<<<dim3((mx + 255) / 256, 4), 256>>>(
            idx2, nnz2, idx3, nnz3, idx4, nnz4, idx5, nnz5);
    }

    // 2) 3-phase exclusive scan
    scan1_kernel<<<NCHUNK, 1024>>>();
    scan2_kernel<<<1, 32>>>();
    scan3_kernel<<<(BINS_TOTAL + 1023) / 1024, 1024>>>();

    // 3) scatter pairs
    scatter1_kernel<<<(nnz1 + 255) / 256, 256>>>(idx1, val1, nnz1);
    {
        int mx = max(max(nnz2, nnz3), max(nnz4, nnz5));
        scatter_small_kernel<<<dim3((mx + 255) / 256, 4), 256>>>(
            idx2, val2, nnz2, idx3, val3, nnz3,
            idx4, val4, nnz4, idx5, val5, nnz5);
    }

    // 4) layer 1: SMEM-tiled SpMM -> partials -> reduce + BN + SiLU
    spmm1_kernel<<<dim3(NCB, NBB), 1024, SPMM1_SMEM>>>(x);
    bn_silu_kernel<<<H1, 512>>>(b1, g1, be1, h1);

    // 5) layers 2..5
    spmm_kernel<<<H1, 512>>>(h1, b2, (const float*)0, (const float*)0, h2, BASE2, 1, H1, 1);
    spmm_kernel<<<H2, 512>>>(h2, b3, g2, be2, h3, BASE3, 2, H2, 1);
    spmm_kernel<<<H3, 512>>>(h3, b4, g3, be3, h4, BASE4, 2, H3, 1);
    spmm_kernel<<<H3, 512>>>(h4, b5, (const float*)0, (const float*)0,
                             (float*)d_out, BASE5, 0, H3, 0);
}

// round 10
// speedup vs baseline: 1.4933x; 1.0698x over previous
#include <cuda_runtime.h>
#include <cstdint>

// ---------------------------------------------------------------------------
// Problem constants
// ---------------------------------------------------------------------------
#define D_IN   120000
#define BATCH  512
#define H1     600
#define H2     300
#define H3     200

// ---------------------------------------------------------------------------
// Layer-1 SMEM-tiled SpMM geometry
// ---------------------------------------------------------------------------
#define COLB   384                  // columns per block (x tile 384x128 fp32)
#define NCB    313                  // ceil(120000/384); last block has 192 cols
#define BB     128                  // batch lanes per CTA
#define NBB    (BATCH / BB)         // 4
#define XTILE_BYTES (COLB * 128 * 4)            // 196608
#define SPMM1_SMEM (XTILE_BYTES + H1 * 4)       // + per-row count cache

// Fixed-capacity bins (no histogram / no scan needed).
// Layer-1 bin = (colblock, row): Poisson(38.4) -> CAP1=128 is >9 sigma safe.
#define BINS1  (NCB * H1)           // 187800
#define CAP1   128                  // slots per layer-1 bin (1KB-aligned)
// Small layers keyed by row: Poisson(<=60) -> CAP_S=256 is enormous margin.
#define SB2    0
#define SB3    (SB2 + H1)           // 600
#define SB4    (SB3 + H2)           // 900
#define SB5    (SB4 + H3)           // 1100
#define BINS_S (SB5 + H3)           // 1300
#define CAP_S  256

// ---------------------------------------------------------------------------
// Static device scratch (allocation-free rule)
// ---------------------------------------------------------------------------
__device__ float2 g_pairs1[(size_t)BINS1 * CAP1];   // 192.3 MB
__device__ float2 g_pairsS[(size_t)BINS_S * CAP_S]; // 2.7 MB
__device__ int    g_cnt1[BINS1];
__device__ int    g_cntS[BINS_S];
__device__ float  g_part[(size_t)NCB * H1 * BATCH]; // 384.6 MB partials [cb][r][b]
__device__ float  g_h1[H1 * BATCH];
__device__ float  g_h2[H1 * BATCH];
__device__ float  g_h3[H2 * BATCH];
__device__ float  g_h4[H3 * BATCH];

// ---------------------------------------------------------------------------
// 0) zero bin counters
// ---------------------------------------------------------------------------
__global__ void zero_cnt_kernel() {
    int i = blockIdx.x * blockDim.x + threadIdx.x;
    if (i < BINS1) g_cnt1[i] = 0;
    if (i < BINS_S) g_cntS[i] = 0;
}

// ---------------------------------------------------------------------------
// 1) scatter layer-1 pairs into capacity bins.
//    pairs.x = precomputed swizzled word offset:
//    word(cl, b) = cl*128 + (b ^ ((cl & 31) << 2)) -> store cl*128 + ((cl&31)<<2)
// ---------------------------------------------------------------------------
__global__ void scatter1_kernel(const int* __restrict__ idx,
                                const float* __restrict__ val, int nnz) {
    int j = blockIdx.x * blockDim.x + threadIdx.x;
    if (j >= nnz) return;
    int r = idx[j];
    int c = idx[nnz + j];
    int cb = c / COLB;
    int cl = c - cb * COLB;
    int key = cb * H1 + r;
    int fill = atomicAdd(&g_cnt1[key], 1);
    if (fill >= CAP1) return;               // statistically impossible; guard
    int px = cl * 128 + ((cl & 31) << 2);
    g_pairs1[(size_t)key * CAP1 + fill] = make_float2(__int_as_float(px), val[j]);
}

// ---------------------------------------------------------------------------
// 2) scatter small-layer pairs (layers 2..5 fused via blockIdx.y)
// ---------------------------------------------------------------------------
__global__ void scatter_small_kernel(
    const int* __restrict__ i2, const float* __restrict__ v2, int n2,
    const int* __restrict__ i3, const float* __restrict__ v3, int n3,
    const int* __restrict__ i4, const float* __restrict__ v4, int n4,
    const int* __restrict__ i5, const float* __restrict__ v5, int n5)
{
    const int* p; const float* v; int n, sb;
    switch (blockIdx.y) {
        case 0: p = i2; v = v2; n = n2; sb = SB2; break;
        case 1: p = i3; v = v3; n = n3; sb = SB3; break;
        case 2: p = i4; v = v4; n = n4; sb = SB4; break;
        default: p = i5; v = v5; n = n5; sb = SB5; break;
    }
    int j = blockIdx.x * blockDim.x + threadIdx.x;
    if (j >= n) return;
    int key = sb + p[j];
    int fill = atomicAdd(&g_cntS[key], 1);
    if (fill >= CAP_S) return;
    g_pairsS[(size_t)key * CAP_S + fill] =
        make_float2(__int_as_float(p[n + j]), v[j]);
}

// ---------------------------------------------------------------------------
// 3) Layer-1 SpMM: CTA = (col-block, batch-block), 1024 threads = 32 warps.
//    x tile (XOR-swizzled) + per-row counts staged in SMEM; pairs streamed as
//    float4 (2 pairs) with 2-deep prefetch; warp w sweeps rows w, w+32, ...
// ---------------------------------------------------------------------------
__global__ void __launch_bounds__(1024, 1) spmm1_kernel(const float* __restrict__ x) {
    extern __shared__ char smem[];
    float* xs  = (float*)smem;
    int* sCnt  = (int*)(smem + XTILE_BYTES);
    const int cb  = blockIdx.x;
    const int bbk = blockIdx.y;
    const int c0 = cb * COLB;
    const int ncols = min(COLB, D_IN - c0);
    const int tid = threadIdx.x;

    // per-row pair counts for this colblock -> SMEM (600 ints)
    for (int i = tid; i < H1; i += 1024)
        sCnt[i] = g_cnt1[cb * H1 + i];

    // x tile [ncols][128] with XOR swizzle; global reads coalesced float4
    {
        const float* xb = x + (size_t)(bbk * BB) * D_IN + c0;
        const int nq = ncols >> 2;
        const int total = nq * BB;
        for (int idx = tid; idx < total; idx += 1024) {
            int cq = idx % nq;
            int b  = idx / nq;
            float4 f = *(const float4*)(xb + (size_t)b * D_IN + 4 * cq);
            int cl = 4 * cq;
#pragma unroll
            for (int j = 0; j < 4; ++j) {
                int clj = cl + j;
                xs[clj * 128 + (b ^ ((clj & 31) << 2))] = (&f.x)[j];
            }
        }
    }
    __syncthreads();

    const int w    = tid >> 5;          // warp 0..31: rows w, w+32, ...
    const int lane = tid & 31;          // batch quad 4*lane .. 4*lane+3
    const uint32_t l4 = (uint32_t)lane << 2;

    for (int r = w; r < H1; r += 32) {
        const int cnt = sCnt[r];
        const float2* binp = g_pairs1 + (size_t)(cb * H1 + r) * CAP1;
        const float4* pq = (const float4*)binp;   // bins are 1KB-aligned
        const int n2 = cnt >> 1;

        float4 acc0 = make_float4(0.f, 0.f, 0.f, 0.f);
        float4 acc1 = make_float4(0.f, 0.f, 0.f, 0.f);

        float4 q, qn;
        if (n2 > 0) q  = __ldg(pq);
        if (n2 > 1) qn = __ldg(pq + 1);
        for (int i = 0; i < n2; ++i) {
            float4 cur = q;
            q = qn;
            if (i + 2 < n2) qn = __ldg(pq + i + 2);
            const float4 v0 = *(const float4*)(xs + (__float_as_uint(cur.x) ^ l4));
            acc0.x += cur.y * v0.x; acc0.y += cur.y * v0.y;
            acc0.z += cur.y * v0.z; acc0.w += cur.y * v0.w;
            const float4 v1 = *(const float4*)(xs + (__float_as_uint(cur.z) ^ l4));
            acc1.x += cur.w * v1.x; acc1.y += cur.w * v1.y;
            acc1.z += cur.w * v1.z; acc1.w += cur.w * v1.w;
        }
        if (cnt & 1) {                   // odd tail pair
            float2 p = __ldg(&binp[cnt - 1]);
            const float4 v = *(const float4*)(xs + (__float_as_uint(p.x) ^ l4));
            acc0.x += p.y * v.x; acc0.y += p.y * v.y;
            acc0.z += p.y * v.z; acc0.w += p.y * v.w;
        }
        float4 acc = make_float4(acc0.x + acc1.x, acc0.y + acc1.y,
                                 acc0.z + acc1.z, acc0.w + acc1.w);
        *(float4*)(g_part + (size_t)(cb * H1 + r) * BATCH + bbk * BB + 4 * lane) = acc;
    }
}

// ---------------------------------------------------------------------------
// 4) reduce colblock partials + bias + BN + SiLU -> g_h1 [r][512]
// ---------------------------------------------------------------------------
__global__ void __launch_bounds__(512) bn_silu_kernel(
    const float* __restrict__ bias, const float* __restrict__ gamma,
    const float* __restrict__ beta, float* __restrict__ out)
{
    int r = blockIdx.x, tid = threadIdx.x;
    const float* p = g_part + (size_t)r * BATCH + tid;
    const size_t stride = (size_t)H1 * BATCH;
    float a0 = 0.f, a1 = 0.f, a2 = 0.f, a3 = 0.f;
    int cbi = 0;
    for (; cbi + 4 <= NCB; cbi += 4) {
        a0 += p[(size_t)(cbi + 0) * stride];
        a1 += p[(size_t)(cbi + 1) * stride];
        a2 += p[(size_t)(cbi + 2) * stride];
        a3 += p[(size_t)(cbi + 3) * stride];
    }
    for (; cbi < NCB; ++cbi) a0 += p[(size_t)cbi * stride];
    float acc = (a0 + a1) + (a2 + a3) + bias[r];

    __shared__ float rsum[16], rsum2[16], bcast[2];
    float s = acc, s2 = acc * acc;
#pragma unroll
    for (int d = 16; d; d >>= 1) {
        s  += __shfl_xor_sync(0xFFFFFFFFu, s, d);
        s2 += __shfl_xor_sync(0xFFFFFFFFu, s2, d);
    }
    int lane = tid & 31, wid = tid >> 5;
    if (lane == 0) { rsum[wid] = s; rsum2[wid] = s2; }
    __syncthreads();
    if (wid == 0) {
        float a   = (lane < 16) ? rsum[lane]  : 0.0f;
        float a2w = (lane < 16) ? rsum2[lane] : 0.0f;
#pragma unroll
        for (int d = 8; d; d >>= 1) {
            a   += __shfl_xor_sync(0xFFFFFFFFu, a, d);
            a2w += __shfl_xor_sync(0xFFFFFFFFu, a2w, d);
        }
        if (lane == 0) { bcast[0] = a; bcast[1] = a2w; }
    }
    __syncthreads();
    float m   = bcast[0] * (1.0f / 512.0f);
    float var = bcast[1] * (1.0f / 512.0f) - m * m;
    float z = (acc - m) * rsqrtf(var + 1e-5f) * gamma[r] + beta[r];
    z = z * (1.0f / (1.0f + __expf(-z)));
    out[r * BATCH + tid] = z;
}

// ---------------------------------------------------------------------------
// 5) small sparse layers 2..5;  mode: 0 = raw, 1 = silu, 2 = bn + silu
//    cnt <= CAP_S = 256 < 512, so a single staging pass suffices.
// ---------------------------------------------------------------------------
__global__ void __launch_bounds__(512) spmm_kernel(
    const float* __restrict__ inT, const float* __restrict__ bias,
    const float* __restrict__ gamma, const float* __restrict__ beta,
    float* __restrict__ out, int sb, int mode, int outDim, int outTransposed)
{
    __shared__ float2 sh[CAP_S];
    int r = blockIdx.x, tid = threadIdx.x;
    const int cnt = g_cntS[sb + r];
    const float2* binp = g_pairsS + (size_t)(sb + r) * CAP_S;

    if (tid < cnt) sh[tid] = binp[tid];
    __syncthreads();

    float acc = 0.0f;
    int k = 0;
    for (; k + 4 <= cnt; k += 4) {
        float2 p0 = sh[k], p1 = sh[k+1], p2 = sh[k+2], p3 = sh[k+3];
        acc += p0.y * inT[__float_as_int(p0.x) * BATCH + tid];
        acc += p1.y * inT[__float_as_int(p1.x) * BATCH + tid];
        acc += p2.y * inT[__float_as_int(p2.x) * BATCH + tid];
        acc += p3.y * inT[__float_as_int(p3.x) * BATCH + tid];
    }
    for (; k < cnt; k++) {
        float2 p = sh[k];
        acc += p.y * inT[__float_as_int(p.x) * BATCH + tid];
    }
    acc += bias[r];

    float z = acc;
    if (mode >= 2) {
        __shared__ float rsum[16], rsum2[16], bcast[2];
        float s = acc, s2 = acc * acc;
#pragma unroll
        for (int d = 16; d; d >>= 1) {
            s  += __shfl_xor_sync(0xFFFFFFFFu, s, d);
            s2 += __shfl_xor_sync(0xFFFFFFFFu, s2, d);
        }
        int lane = tid & 31, wid = tid >> 5;
        if (lane == 0) { rsum[wid] = s; rsum2[wid] = s2; }
        __syncthreads();
        if (wid == 0) {
            float a  = (lane < 16) ? rsum[lane]  : 0.0f;
            float a2 = (lane < 16) ? rsum2[lane] : 0.0f;
#pragma unroll
            for (int d = 8; d; d >>= 1) {
                a  += __shfl_xor_sync(0xFFFFFFFFu, a, d);
                a2 += __shfl_xor_sync(0xFFFFFFFFu, a2, d);
            }
            if (lane == 0) { bcast[0] = a; bcast[1] = a2; }
        }
        __syncthreads();
        float m   = bcast[0] * (1.0f / 512.0f);
        float var = bcast[1] * (1.0f / 512.0f) - m * m;
        z = (acc - m) * rsqrtf(var + 1e-5f) * gamma[r] + beta[r];
    }
    if (mode >= 1) z = z * (1.0f / (1.0f + __expf(-z)));
    if (outTransposed) out[r * BATCH + tid] = z;
    else               out[(size_t)tid * outDim + r] = z;
}

// ---------------------------------------------------------------------------
// kernel_launch: kernel launches only (graph-capturable)
// ---------------------------------------------------------------------------
extern "C" void kernel_launch(void* const* d_in, const int* in_sizes, int n_in,
                              void* d_out, int out_size) {
    const float* x    = (const float*)d_in[0];
    const int*   idx1 = (const int*)  d_in[1];
    const float* val1 = (const float*)d_in[2];
    const float* b1   = (const float*)d_in[3];
    const int*   idx2 = (const int*)  d_in[4];
    const float* val2 = (const float*)d_in[5];
    const float* b2   = (const float*)d_in[6];
    const int*   idx3 = (const int*)  d_in[7];
    const float* val3 = (const float*)d_in[8];
    const float* b3   = (const float*)d_in[9];
    const int*   idx4 = (const int*)  d_in[10];
    const float* val4 = (const float*)d_in[11];
    const float* b4   = (const float*)d_in[12];
    const int*   idx5 = (const int*)  d_in[13];
    const float* val5 = (const float*)d_in[14];
    const float* b5   = (const float*)d_in[15];
    const float* g1   = (const float*)d_in[16];
    const float* be1  = (const float*)d_in[17];
    const float* g2   = (const float*)d_in[18];
    const float* be2  = (const float*)d_in[19];
    const float* g3   = (const float*)d_in[20];
    const float* be3  = (const float*)d_in[21];

    int nnz1 = in_sizes[1]  / 2;
    int nnz2 = in_sizes[4]  / 2;
    int nnz3 = in_sizes[7]  / 2;
    int nnz4 = in_sizes[10] / 2;
    int nnz5 = in_sizes[13] / 2;

    float *h1, *h2, *h3, *h4;
    cudaGetSymbolAddress((void**)&h1, g_h1);
    cudaGetSymbolAddress((void**)&h2, g_h2);
    cudaGetSymbolAddress((void**)&h3, g_h3);
    cudaGetSymbolAddress((void**)&h4, g_h4);

    cudaFuncSetAttribute(spmm1_kernel,
                         cudaFuncAttributeMaxDynamicSharedMemorySize, SPMM1_SMEM);

    // 0) zero bin counters
    zero_cnt_kernel<<<(BINS1 + 255) / 256, 256>>>();

    // 1) scatter pairs into fixed-capacity bins (no hist / no scan)
    scatter1_kernel<<<(nnz1 + 255) / 256, 256>>>(idx1, val1, nnz1);
    {
        int mx = max(max(nnz2, nnz3), max(nnz4, nnz5));
        scatter_small_kernel<<<dim3((mx + 255) / 256, 4), 256>>>(
            idx2, val2, nnz2, idx3, val3, nnz3,
            idx4, val4, nnz4, idx5, val5, nnz5);
    }

    // 2) layer 1: SMEM-tiled SpMM -> partials -> reduce + BN + SiLU
    spmm1_kernel<<<dim3(NCB, NBB), 1024, SPMM1_SMEM>>>(x);
    bn_silu_kernel<<<H1, 512>>>(b1, g1, be1, h1);

    // 3) layers 2..5
    spmm_kernel<<<H1, 512>>>(h1, b2, (const float*)0, (const float*)0, h2, SB2, 1, H1, 1);
    spmm_kernel<<<H2, 512>>>(h2, b3, g2, be2, h3, SB3, 2, H2, 1);
    spmm_kernel<<<H3, 512>>>(h3, b4, g3, be3, h4, SB4, 2, H3, 1);
    spmm_kernel<<<H3, 512>>>(h4, b5, (const float*)0, (const float*)0,
                             (float*)d_out, SB5, 0, H3, 0);
}

// round 12
// speedup vs baseline: 1.6483x; 1.1038x over previous
#include <cuda_runtime.h>
#include <cstdint>

// ---------------------------------------------------------------------------
// Problem constants
// ---------------------------------------------------------------------------
#define D_IN   120000
#define BATCH  512
#define H1     600
#define H2     300
#define H3     200

// ---------------------------------------------------------------------------
// Layer-1 SMEM-tiled SpMM geometry
// ---------------------------------------------------------------------------
#define COLB   384                  // columns per block (x tile 384x128 fp32)
#define NCB    313                  // ceil(120000/384); last block has 192 cols
#define BB     128                  // batch lanes per CTA
#define NBB    (BATCH / BB)         // 4
#define XTILE_BYTES (COLB * 128 * 4)            // 196608
#define SPMM1_SMEM (XTILE_BYTES + H1 * 4)       // + per-row count cache

// Fixed-capacity bins (no histogram / no scan needed).
// Layer-1 bin = (colblock, row): Poisson(38.4) -> CAP1=128 is >9 sigma safe.
#define BINS1  (NCB * H1)           // 187800
#define CAP1   128                  // slots per layer-1 bin (1KB-aligned)
// Small layers keyed by row: Poisson(<=60) -> CAP_S=256 is enormous margin.
#define SB2    0
#define SB3    (SB2 + H1)           // 600
#define SB4    (SB3 + H2)           // 900
#define SB5    (SB4 + H3)           // 1100
#define BINS_S (SB5 + H3)           // 1300
#define CAP_S  256

// Swizzle: word(cl, b) = cl*128 + (b ^ perm(cl)),  perm(cl) = ((cl>>2)&31)<<2
//  - gather (fixed cl, b = 4*lane..4*lane+3): perm ^ 4l is a bijection over the
//    32 16B groups -> conflict-free LDS.128
//  - store  (fixed b, cl = 4*cq+j, cq consecutive across lanes): bank =
//    (b ^ ((cq&31)<<2)) & 31 -> 8 distinct banks -> 4-way (was 16-way)
#define PERM(cl) ((((cl) >> 2) & 31) << 2)

// ---------------------------------------------------------------------------
// Static device scratch (allocation-free rule)
// ---------------------------------------------------------------------------
__device__ float2 g_pairs1[(size_t)BINS1 * CAP1];   // 192.3 MB
__device__ float2 g_pairsS[(size_t)BINS_S * CAP_S]; // 2.7 MB
__device__ int    g_cnt1[BINS1];
__device__ int    g_cntS[BINS_S];
__device__ float  g_part[(size_t)NCB * H1 * BATCH]; // 384.6 MB partials [cb][r][b]
__device__ float  g_h1[H1 * BATCH];
__device__ float  g_h2[H1 * BATCH];
__device__ float  g_h3[H2 * BATCH];
__device__ float  g_h4[H3 * BATCH];

// ---------------------------------------------------------------------------
// 0) zero bin counters
// ---------------------------------------------------------------------------
__global__ void zero_cnt_kernel() {
    int i = blockIdx.x * blockDim.x + threadIdx.x;
    if (i < BINS1) g_cnt1[i] = 0;
    if (i < BINS_S) g_cntS[i] = 0;
}

// ---------------------------------------------------------------------------
// 1) scatter layer-1 pairs into capacity bins.
//    pairs.x = precomputed swizzled word offset cl*128 + PERM(cl)
// ---------------------------------------------------------------------------
__global__ void scatter1_kernel(const int* __restrict__ idx,
                                const float* __restrict__ val, int nnz) {
    int j = blockIdx.x * blockDim.x + threadIdx.x;
    if (j >= nnz) return;
    int r = idx[j];
    int c = idx[nnz + j];
    int cb = c / COLB;
    int cl = c - cb * COLB;
    int key = cb * H1 + r;
    int fill = atomicAdd(&g_cnt1[key], 1);
    if (fill >= CAP1) return;               // statistically impossible; guard
    int px = cl * 128 + PERM(cl);
    g_pairs1[(size_t)key * CAP1 + fill] = make_float2(__int_as_float(px), val[j]);
}

// ---------------------------------------------------------------------------
// 2) scatter small-layer pairs (layers 2..5 fused via blockIdx.y)
// ---------------------------------------------------------------------------
__global__ void scatter_small_kernel(
    const int* __restrict__ i2, const float* __restrict__ v2, int n2,
    const int* __restrict__ i3, const float* __restrict__ v3, int n3,
    const int* __restrict__ i4, const float* __restrict__ v4, int n4,
    const int* __restrict__ i5, const float* __restrict__ v5, int n5)
{
    const int* p; const float* v; int n, sb;
    switch (blockIdx.y) {
        case 0: p = i2; v = v2; n = n2; sb = SB2; break;
        case 1: p = i3; v = v3; n = n3; sb = SB3; break;
        case 2: p = i4; v = v4; n = n4; sb = SB4; break;
        default: p = i5; v = v5; n = n5; sb = SB5; break;
    }
    int j = blockIdx.x * blockDim.x + threadIdx.x;
    if (j >= n) return;
    int key = sb + p[j];
    int fill = atomicAdd(&g_cntS[key], 1);
    if (fill >= CAP_S) return;
    g_pairsS[(size_t)key * CAP_S + fill] =
        make_float2(__int_as_float(p[n + j]), v[j]);
}

// ---------------------------------------------------------------------------
// 3) Layer-1 SpMM: CTA = (col-block, batch-block), 1024 threads = 32 warps.
//    x tile (swizzled, 4-way-max store conflicts, conflict-free gather) +
//    per-row counts staged in SMEM; pairs streamed as float4 (2 pairs) with
//    2-deep prefetch; warp w sweeps rows w, w+32, ...
// ---------------------------------------------------------------------------
__global__ void __launch_bounds__(1024, 1) spmm1_kernel(const float* __restrict__ x) {
    extern __shared__ char smem[];
    float* xs  = (float*)smem;
    int* sCnt  = (int*)(smem + XTILE_BYTES);
    const int cb  = blockIdx.x;
    const int bbk = blockIdx.y;
    const int c0 = cb * COLB;
    const int ncols = min(COLB, D_IN - c0);
    const int tid = threadIdx.x;

    // per-row pair counts for this colblock -> SMEM (600 ints)
    for (int i = tid; i < H1; i += 1024)
        sCnt[i] = g_cnt1[cb * H1 + i];

    // x tile [ncols][128] swizzled; global reads coalesced float4
    {
        const float* xb = x + (size_t)(bbk * BB) * D_IN + c0;
        const int nq = ncols >> 2;
        const int total = nq * BB;
        for (int idx = tid; idx < total; idx += 1024) {
            int cq = idx % nq;
            int b  = idx / nq;
            float4 f = __ldcs((const float4*)(xb + (size_t)b * D_IN + 4 * cq));
            // perm depends only on cq -> constant across the 4 stores
            int base = (4 * cq) * 128 + (b ^ (((cq) & 31) << 2));
            xs[base + 0 * 128] = f.x;
            xs[base + 1 * 128] = f.y;
            xs[base + 2 * 128] = f.z;
            xs[base + 3 * 128] = f.w;
        }
    }
    __syncthreads();

    const int w    = tid >> 5;          // warp 0..31: rows w, w+32, ...
    const int lane = tid & 31;          // batch quad 4*lane .. 4*lane+3
    const uint32_t l4 = (uint32_t)lane << 2;

    for (int r = w; r < H1; r += 32) {
        const int cnt = sCnt[r];
        const float2* binp = g_pairs1 + (size_t)(cb * H1 + r) * CAP1;
        const float4* pq = (const float4*)binp;   // bins are 1KB-aligned
        const int n2 = cnt >> 1;

        float4 acc0 = make_float4(0.f, 0.f, 0.f, 0.f);
        float4 acc1 = make_float4(0.f, 0.f, 0.f, 0.f);

        float4 q, qn;
        if (n2 > 0) q  = __ldg(pq);
        if (n2 > 1) qn = __ldg(pq + 1);
        for (int i = 0; i < n2; ++i) {
            float4 cur = q;
            q = qn;
            if (i + 2 < n2) qn = __ldg(pq + i + 2);
            const float4 v0 = *(const float4*)(xs + (__float_as_uint(cur.x) ^ l4));
            acc0.x += cur.y * v0.x; acc0.y += cur.y * v0.y;
            acc0.z += cur.y * v0.z; acc0.w += cur.y * v0.w;
            const float4 v1 = *(const float4*)(xs + (__float_as_uint(cur.z) ^ l4));
            acc1.x += cur.w * v1.x; acc1.y += cur.w * v1.y;
            acc1.z += cur.w * v1.z; acc1.w += cur.w * v1.w;
        }
        if (cnt & 1) {                   // odd tail pair
            float2 p = __ldg(&binp[cnt - 1]);
            const float4 v = *(const float4*)(xs + (__float_as_uint(p.x) ^ l4));
            acc0.x += p.y * v.x; acc0.y += p.y * v.y;
            acc0.z += p.y * v.z; acc0.w += p.y * v.w;
        }
        float4 acc = make_float4(acc0.x + acc1.x, acc0.y + acc1.y,
                                 acc0.z + acc1.z, acc0.w + acc1.w);
        __stcs((float4*)(g_part + (size_t)(cb * H1 + r) * BATCH
                         + bbk * BB + 4 * lane), acc);
    }
}

// ---------------------------------------------------------------------------
// 4) reduce colblock partials + bias + BN + SiLU -> g_h1 [r][512]
// ---------------------------------------------------------------------------
__global__ void __launch_bounds__(512) bn_silu_kernel(
    const float* __restrict__ bias, const float* __restrict__ gamma,
    const float* __restrict__ beta, float* __restrict__ out)
{
    int r = blockIdx.x, tid = threadIdx.x;
    const float* p = g_part + (size_t)r * BATCH + tid;
    const size_t stride = (size_t)H1 * BATCH;
    float a0 = 0.f, a1 = 0.f, a2 = 0.f, a3 = 0.f;
    int cbi = 0;
    for (; cbi + 4 <= NCB; cbi += 4) {
        a0 += __ldcs(p + (size_t)(cbi + 0) * stride);
        a1 += __ldcs(p + (size_t)(cbi + 1) * stride);
        a2 += __ldcs(p + (size_t)(cbi + 2) * stride);
        a3 += __ldcs(p + (size_t)(cbi + 3) * stride);
    }
    for (; cbi < NCB; ++cbi) a0 += __ldcs(p + (size_t)cbi * stride);
    float acc = (a0 + a1) + (a2 + a3) + bias[r];

    __shared__ float rsum[16], rsum2[16], bcast[2];
    float s = acc, s2 = acc * acc;
#pragma unroll
    for (int d = 16; d; d >>= 1) {
        s  += __shfl_xor_sync(0xFFFFFFFFu, s, d);
        s2 += __shfl_xor_sync(0xFFFFFFFFu, s2, d);
    }
    int lane = tid & 31, wid = tid >> 5;
    if (lane == 0) { rsum[wid] = s; rsum2[wid] = s2; }
    __syncthreads();
    if (wid == 0) {
        float a   = (lane < 16) ? rsum[lane]  : 0.0f;
        float a2w = (lane < 16) ? rsum2[lane] : 0.0f;
#pragma unroll
        for (int d = 8; d; d >>= 1) {
            a   += __shfl_xor_sync(0xFFFFFFFFu, a, d);
            a2w += __shfl_xor_sync(0xFFFFFFFFu, a2w, d);
        }
        if (lane == 0) { bcast[0] = a; bcast[1] = a2w; }
    }
    __syncthreads();
    float m   = bcast[0] * (1.0f / 512.0f);
    float var = bcast[1] * (1.0f / 512.0f) - m * m;
    float z = (acc - m) * rsqrtf(var + 1e-5f) * gamma[r] + beta[r];
    z = z * (1.0f / (1.0f + __expf(-z)));
    out[r * BATCH + tid] = z;
}

// ---------------------------------------------------------------------------
// 5) small sparse layers 2..5;  mode: 0 = raw, 1 = silu, 2 = bn + silu
//    cnt <= CAP_S = 256 < 512, so a single staging pass suffices.
// ---------------------------------------------------------------------------
__global__ void __launch_bounds__(512) spmm_kernel(
    const float* __restrict__ inT, const float* __restrict__ bias,
    const float* __restrict__ gamma, const float* __restrict__ beta,
    float* __restrict__ out, int sb, int mode, int outDim, int outTransposed)
{
    __shared__ float2 sh[CAP_S];
    int r = blockIdx.x, tid = threadIdx.x;
    const int cnt = g_cntS[sb + r];
    const float2* binp = g_pairsS + (size_t)(sb + r) * CAP_S;

    if (tid < cnt) sh[tid] = binp[tid];
    __syncthreads();

    float acc = 0.0f;
    int k = 0;
    for (; k + 4 <= cnt; k += 4) {
        float2 p0 = sh[k], p1 = sh[k+1], p2 = sh[k+2], p3 = sh[k+3];
        acc += p0.y * inT[__float_as_int(p0.x) * BATCH + tid];
        acc += p1.y * inT[__float_as_int(p1.x) * BATCH + tid];
        acc += p2.y * inT[__float_as_int(p2.x) * BATCH + tid];
        acc += p3.y * inT[__float_as_int(p3.x) * BATCH + tid];
    }
    for (; k < cnt; k++) {
        float2 p = sh[k];
        acc += p.y * inT[__float_as_int(p.x) * BATCH + tid];
    }
    acc += bias[r];

    float z = acc;
    if (mode >= 2) {
        __shared__ float rsum[16], rsum2[16], bcast[2];
        float s = acc, s2 = acc * acc;
#pragma unroll
        for (int d = 16; d; d >>= 1) {
            s  += __shfl_xor_sync(0xFFFFFFFFu, s, d);
            s2 += __shfl_xor_sync(0xFFFFFFFFu, s2, d);
        }
        int lane = tid & 31, wid = tid >> 5;
        if (lane == 0) { rsum[wid] = s; rsum2[wid] = s2; }
        __syncthreads();
        if (wid == 0) {
            float a  = (lane < 16) ? rsum[lane]  : 0.0f;
            float a2 = (lane < 16) ? rsum2[lane] : 0.0f;
#pragma unroll
            for (int d = 8; d; d >>= 1) {
                a  += __shfl_xor_sync(0xFFFFFFFFu, a, d);
                a2 += __shfl_xor_sync(0xFFFFFFFFu, a2, d);
            }
            if (lane == 0) { bcast[0] = a; bcast[1] = a2; }
        }
        __syncthreads();
        float m   = bcast[0] * (1.0f / 512.0f);
        float var = bcast[1] * (1.0f / 512.0f) - m * m;
        z = (acc - m) * rsqrtf(var + 1e-5f) * gamma[r] + beta[r];
    }
    if (mode >= 1) z = z * (1.0f / (1.0f + __expf(-z)));
    if (outTransposed) out[r * BATCH + tid] = z;
    else               out[(size_t)tid * outDim + r] = z;
}

// ---------------------------------------------------------------------------
// kernel_launch: kernel launches only (graph-capturable)
// ---------------------------------------------------------------------------
extern "C" void kernel_launch(void* const* d_in, const int* in_sizes, int n_in,
                              void* d_out, int out_size) {
    const float* x    = (const float*)d_in[0];
    const int*   idx1 = (const int*)  d_in[1];
    const float* val1 = (const float*)d_in[2];
    const float* b1   = (const float*)d_in[3];
    const int*   idx2 = (const int*)  d_in[4];
    const float* val2 = (const float*)d_in[5];
    const float* b2   = (const float*)d_in[6];
    const int*   idx3 = (const int*)  d_in[7];
    const float* val3 = (const float*)d_in[8];
    const float* b3   = (const float*)d_in[9];
    const int*   idx4 = (const int*)  d_in[10];
    const float* val4 = (const float*)d_in[11];
    const float* b4   = (const float*)d_in[12];
    const int*   idx5 = (const int*)  d_in[13];
    const float* val5 = (const float*)d_in[14];
    const float* b5   = (const float*)d_in[15];
    const float* g1   = (const float*)d_in[16];
    const float* be1  = (const float*)d_in[17];
    const float* g2   = (const float*)d_in[18];
    const float* be2  = (const float*)d_in[19];
    const float* g3   = (const float*)d_in[20];
    const float* be3  = (const float*)d_in[21];

    int nnz1 = in_sizes[1]  / 2;
    int nnz2 = in_sizes[4]  / 2;
    int nnz3 = in_sizes[7]  / 2;
    int nnz4 = in_sizes[10] / 2;
    int nnz5 = in_sizes[13] / 2;

    float *h1, *h2, *h3, *h4;
    cudaGetSymbolAddress((void**)&h1, g_h1);
    cudaGetSymbolAddress((void**)&h2, g_h2);
    cudaGetSymbolAddress((void**)&h3, g_h3);
    cudaGetSymbolAddress((void**)&h4, g_h4);

    cudaFuncSetAttribute(spmm1_kernel,
                         cudaFuncAttributeMaxDynamicSharedMemorySize, SPMM1_SMEM);

    // 0) zero bin counters
    zero_cnt_kernel<<<(BINS1 + 255) / 256, 256>>>();

    // 1) scatter pairs into fixed-capacity bins (no hist / no scan)
    scatter1_kernel<<<(nnz1 + 255) / 256, 256>>>(idx1, val1, nnz1);
    {
        int mx = max(max(nnz2, nnz3), max(nnz4, nnz5));
        scatter_small_kernel<<<dim3((mx + 255) / 256, 4), 256>>>(
            idx2, val2, nnz2, idx3, val3, nnz3,
            idx4, val4, nnz4, idx5, val5, nnz5);
    }

    // 2) layer 1: SMEM-tiled SpMM -> partials -> reduce + BN + SiLU
    spmm1_kernel<<<dim3(NCB, NBB), 1024, SPMM1_SMEM>>>(x);
    bn_silu_kernel<<<H1, 512>>>(b1, g1, be1, h1);

    // 3) layers 2..5
    spmm_kernel<<<H1, 512>>>(h1, b2, (const float*)0, (const float*)0, h2, SB2, 1, H1, 1);
    spmm_kernel<<<H2, 512>>>(h2, b3, g2, be2, h3, SB3, 2, H2, 1);
    spmm_kernel<<<H3, 512>>>(h3, b4, g3, be3, h4, SB4, 2, H3, 1);
    spmm_kernel<<<H3, 512>>>(h4, b5, (const float*)0, (const float*)0,
                             (float*)d_out, SB5, 0, H3, 0);
}

// round 13
// speedup vs baseline: 1.6644x; 1.0098x over previous
#include <cuda_runtime.h>
#include <cstdint>

// ---------------------------------------------------------------------------
// Problem constants
// ---------------------------------------------------------------------------
#define D_IN   120000
#define BATCH  512
#define H1     600
#define H2     300
#define H3     200

// ---------------------------------------------------------------------------
// Layer-1 SMEM-tiled SpMM geometry
// ---------------------------------------------------------------------------
#define COLB   384                  // columns per block (x tile 384x128 fp32)
#define NCB    313                  // ceil(120000/384); last block has 192 cols
#define BB     128                  // batch lanes per CTA
#define NBB    (BATCH / BB)         // 4
#define XTILE_BYTES (COLB * 128 * 4)            // 196608
#define SPMM1_SMEM (XTILE_BYTES + H1 * 4)       // + per-row count cache

// Fixed-capacity bins (no histogram / no scan needed).
// Layer-1 bin = (colblock, row): Poisson(38.4) -> CAP1=128 is >9 sigma safe.
#define BINS1  (NCB * H1)           // 187800
#define CAP1   128                  // slots per layer-1 bin (1KB-aligned)
// Small layers keyed by row: Poisson(<=60) -> CAP_S=256 is enormous margin.
#define SB2    0
#define SB3    (SB2 + H1)           // 600
#define SB4    (SB3 + H2)           // 900
#define SB5    (SB4 + H3)           // 1100
#define BINS_S (SB5 + H3)           // 1300
#define CAP_S  256

// Swizzle: word(cl, b) = cl*128 + (b ^ perm(cl)),  perm(cl) = ((cl>>2)&31)<<2
//  - gather (fixed cl, b = 4*lane..4*lane+3): perm ^ 4l is a bijection over the
//    32 16B groups -> conflict-free LDS.128
//  - store  (fixed b, cl = 4*cq+j, cq consecutive across lanes): bank =
//    (b ^ ((cq&31)<<2)) & 31 -> 8 distinct banks -> 4-way (was 16-way)
#define PERM(cl) ((((cl) >> 2) & 31) << 2)

// ---------------------------------------------------------------------------
// Static device scratch (allocation-free rule).  +8 pad slots: the inner-loop
// prefetch may read up to 2 float4 (4 pairs) past the last bin.
// ---------------------------------------------------------------------------
__device__ float2 g_pairs1[(size_t)BINS1 * CAP1 + 8];   // 192.3 MB
__device__ float2 g_pairsS[(size_t)BINS_S * CAP_S];     // 2.7 MB
__device__ int    g_cnt1[BINS1];
__device__ int    g_cntS[BINS_S];
__device__ float  g_part[(size_t)NCB * H1 * BATCH];     // 384.6 MB [cb][r][b]
__device__ float  g_h1[H1 * BATCH];
__device__ float  g_h2[H1 * BATCH];
__device__ float  g_h3[H2 * BATCH];
__device__ float  g_h4[H3 * BATCH];

// ---------------------------------------------------------------------------
// 0) zero bin counters
// ---------------------------------------------------------------------------
__global__ void zero_cnt_kernel() {
    int i = blockIdx.x * blockDim.x + threadIdx.x;
    if (i < BINS1) g_cnt1[i] = 0;
    if (i < BINS_S) g_cntS[i] = 0;
}

// ---------------------------------------------------------------------------
// 1) scatter layer-1 pairs into capacity bins.
//    pairs.x = precomputed swizzled word offset cl*128 + PERM(cl)
// ---------------------------------------------------------------------------
__global__ void scatter1_kernel(const int* __restrict__ idx,
                                const float* __restrict__ val, int nnz) {
    int j = blockIdx.x * blockDim.x + threadIdx.x;
    if (j >= nnz) return;
    int r = idx[j];
    int c = idx[nnz + j];
    int cb = c / COLB;
    int cl = c - cb * COLB;
    int key = cb * H1 + r;
    int fill = atomicAdd(&g_cnt1[key], 1);
    if (fill >= CAP1 - 2) return;            // statistically impossible; guard
    int px = cl * 128 + PERM(cl);
    g_pairs1[(size_t)key * CAP1 + fill] = make_float2(__int_as_float(px), val[j]);
}

// ---------------------------------------------------------------------------
// 1b) pad bins: clamp count and zero the pair after the last one when cnt is
//     odd, so the SpMM loop runs whole float4s with no tail branch.
// ---------------------------------------------------------------------------
__global__ void pad_bins_kernel() {
    int key = blockIdx.x * blockDim.x + threadIdx.x;
    if (key >= BINS1) return;
    int cnt = g_cnt1[key];
    if (cnt > CAP1 - 2) { cnt = CAP1 - 2; g_cnt1[key] = cnt; }
    if (cnt & 1)
        g_pairs1[(size_t)key * CAP1 + cnt] = make_float2(0.f, 0.f);
}

// ---------------------------------------------------------------------------
// 2) scatter small-layer pairs (layers 2..5 fused via blockIdx.y)
// ---------------------------------------------------------------------------
__global__ void scatter_small_kernel(
    const int* __restrict__ i2, const float* __restrict__ v2, int n2,
    const int* __restrict__ i3, const float* __restrict__ v3, int n3,
    const int* __restrict__ i4, const float* __restrict__ v4, int n4,
    const int* __restrict__ i5, const float* __restrict__ v5, int n5)
{
    const int* p; const float* v; int n, sb;
    switch (blockIdx.y) {
        case 0: p = i2; v = v2; n = n2; sb = SB2; break;
        case 1: p = i3; v = v3; n = n3; sb = SB3; break;
        case 2: p = i4; v = v4; n = n4; sb = SB4; break;
        default: p = i5; v = v5; n = n5; sb = SB5; break;
    }
    int j = blockIdx.x * blockDim.x + threadIdx.x;
    if (j >= n) return;
    int key = sb + p[j];
    int fill = atomicAdd(&g_cntS[key], 1);
    if (fill >= CAP_S) return;
    g_pairsS[(size_t)key * CAP_S + fill] =
        make_float2(__int_as_float(p[n + j]), v[j]);
}

// ---------------------------------------------------------------------------
// 3) Layer-1 SpMM: CTA = (col-block, batch-block), 1024 threads = 32 warps.
//    x tile (swizzled) + per-row counts in SMEM; pairs streamed as float4
//    (2 pairs) with branch-free 2-deep prefetch (bins zero-padded to even);
//    warp w sweeps rows w, w+32, ...
// ---------------------------------------------------------------------------
__global__ void __launch_bounds__(1024, 1) spmm1_kernel(const float* __restrict__ x) {
    extern __shared__ char smem[];
    float* xs  = (float*)smem;
    int* sCnt  = (int*)(smem + XTILE_BYTES);
    const int cb  = blockIdx.x;
    const int bbk = blockIdx.y;
    const int c0 = cb * COLB;
    const int ncols = min(COLB, D_IN - c0);
    const int tid = threadIdx.x;

    // per-row pair counts for this colblock -> SMEM (600 ints)
    for (int i = tid; i < H1; i += 1024)
        sCnt[i] = g_cnt1[cb * H1 + i];

    // x tile [ncols][128] swizzled; global reads coalesced float4
    {
        const float* xb = x + (size_t)(bbk * BB) * D_IN + c0;
        const int nq = ncols >> 2;
        const int total = nq * BB;
        for (int idx = tid; idx < total; idx += 1024) {
            int cq = idx % nq;
            int b  = idx / nq;
            float4 f = __ldcs((const float4*)(xb + (size_t)b * D_IN + 4 * cq));
            // perm depends only on cq -> constant across the 4 stores
            int base = (4 * cq) * 128 + (b ^ (((cq) & 31) << 2));
            xs[base + 0 * 128] = f.x;
            xs[base + 1 * 128] = f.y;
            xs[base + 2 * 128] = f.z;
            xs[base + 3 * 128] = f.w;
        }
    }
    __syncthreads();

    const int w    = tid >> 5;          // warp 0..31: rows w, w+32, ...
    const int lane = tid & 31;          // batch quad 4*lane .. 4*lane+3
    const uint32_t l4 = (uint32_t)lane << 2;

    for (int r = w; r < H1; r += 32) {
        const int cnt = sCnt[r];        // bin padded: odd slot holds val=0
        const int nQ  = (cnt + 1) >> 1; // whole float4 iterations, no tail
        const float4* pq = (const float4*)(g_pairs1 + (size_t)(cb * H1 + r) * CAP1);

        float4 acc0 = make_float4(0.f, 0.f, 0.f, 0.f);
        float4 acc1 = make_float4(0.f, 0.f, 0.f, 0.f);

        if (nQ > 0) {
            float4 q  = __ldg(pq);      // slot 1 always within the 64-slot bin
            float4 qn = __ldg(pq + 1);
            for (int i = 0; i < nQ; ++i) {
                float4 cur = q;
                q = qn;
                qn = __ldg(pq + i + 2); // unconditional: overshoot is loaded
                                        // but never used (global array padded)
                const float4 v0 = *(const float4*)(xs + (__float_as_uint(cur.x) ^ l4));
                acc0.x += cur.y * v0.x; acc0.y += cur.y * v0.y;
                acc0.z += cur.y * v0.z; acc0.w += cur.y * v0.w;
                const float4 v1 = *(const float4*)(xs + (__float_as_uint(cur.z) ^ l4));
                acc1.x += cur.w * v1.x; acc1.y += cur.w * v1.y;
                acc1.z += cur.w * v1.z; acc1.w += cur.w * v1.w;
            }
        }
        float4 acc = make_float4(acc0.x + acc1.x, acc0.y + acc1.y,
                                 acc0.z + acc1.z, acc0.w + acc1.w);
        __stcs((float4*)(g_part + (size_t)(cb * H1 + r) * BATCH
                         + bbk * BB + 4 * lane), acc);
    }
}

// ---------------------------------------------------------------------------
// 4) reduce colblock partials + bias + BN + SiLU -> g_h1 [r][512]
// ---------------------------------------------------------------------------
__global__ void __launch_bounds__(512) bn_silu_kernel(
    const float* __restrict__ bias, const float* __restrict__ gamma,
    const float* __restrict__ beta, float* __restrict__ out)
{
    int r = blockIdx.x, tid = threadIdx.x;
    const float* p = g_part + (size_t)r * BATCH + tid;
    const size_t stride = (size_t)H1 * BATCH;
    float a0 = 0.f, a1 = 0.f, a2 = 0.f, a3 = 0.f;
    int cbi = 0;
    for (; cbi + 4 <= NCB; cbi += 4) {
        a0 += __ldcs(p + (size_t)(cbi + 0) * stride);
        a1 += __ldcs(p + (size_t)(cbi + 1) * stride);
        a2 += __ldcs(p + (size_t)(cbi + 2) * stride);
        a3 += __ldcs(p + (size_t)(cbi + 3) * stride);
    }
    for (; cbi < NCB; ++cbi) a0 += __ldcs(p + (size_t)cbi * stride);
    float acc = (a0 + a1) + (a2 + a3) + bias[r];

    __shared__ float rsum[16], rsum2[16], bcast[2];
    float s = acc, s2 = acc * acc;
#pragma unroll
    for (int d = 16; d; d >>= 1) {
        s  += __shfl_xor_sync(0xFFFFFFFFu, s, d);
        s2 += __shfl_xor_sync(0xFFFFFFFFu, s2, d);
    }
    int lane = tid & 31, wid = tid >> 5;
    if (lane == 0) { rsum[wid] = s; rsum2[wid] = s2; }
    __syncthreads();
    if (wid == 0) {
        float a   = (lane < 16) ? rsum[lane]  : 0.0f;
        float a2w = (lane < 16) ? rsum2[lane] : 0.0f;
#pragma unroll
        for (int d = 8; d; d >>= 1) {
            a   += __shfl_xor_sync(0xFFFFFFFFu, a, d);
            a2w += __shfl_xor_sync(0xFFFFFFFFu, a2w, d);
        }
        if (lane == 0) { bcast[0] = a; bcast[1] = a2w; }
    }
    __syncthreads();
    float m   = bcast[0] * (1.0f / 512.0f);
    float var = bcast[1] * (1.0f / 512.0f) - m * m;
    float z = (acc - m) * rsqrtf(var + 1e-5f) * gamma[r] + beta[r];
    z = z * (1.0f / (1.0f + __expf(-z)));
    out[r * BATCH + tid] = z;
}

// ---------------------------------------------------------------------------
// 5) small sparse layers 2..5;  mode: 0 = raw, 1 = silu, 2 = bn + silu
//    cnt <= CAP_S = 256 < 512, so a single staging pass suffices.
// ---------------------------------------------------------------------------
__global__ void __launch_bounds__(512) spmm_kernel(
    const float* __restrict__ inT, const float* __restrict__ bias,
    const float* __restrict__ gamma, const float* __restrict__ beta,
    float* __restrict__ out, int sb, int mode, int outDim, int outTransposed)
{
    __shared__ float2 sh[CAP_S];
    int r = blockIdx.x, tid = threadIdx.x;
    const int cnt = g_cntS[sb + r];
    const float2* binp = g_pairsS + (size_t)(sb + r) * CAP_S;

    if (tid < cnt) sh[tid] = binp[tid];
    __syncthreads();

    float acc = 0.0f;
    int k = 0;
    for (; k + 4 <= cnt; k += 4) {
        float2 p0 = sh[k], p1 = sh[k+1], p2 = sh[k+2], p3 = sh[k+3];
        acc += p0.y * inT[__float_as_int(p0.x) * BATCH + tid];
        acc += p1.y * inT[__float_as_int(p1.x) * BATCH + tid];
        acc += p2.y * inT[__float_as_int(p2.x) * BATCH + tid];
        acc += p3.y * inT[__float_as_int(p3.x) * BATCH + tid];
    }
    for (; k < cnt; k++) {
        float2 p = sh[k];
        acc += p.y * inT[__float_as_int(p.x) * BATCH + tid];
    }
    acc += bias[r];

    float z = acc;
    if (mode >= 2) {
        __shared__ float rsum[16], rsum2[16], bcast[2];
        float s = acc, s2 = acc * acc;
#pragma unroll
        for (int d = 16; d; d >>= 1) {
            s  += __shfl_xor_sync(0xFFFFFFFFu, s, d);
            s2 += __shfl_xor_sync(0xFFFFFFFFu, s2, d);
        }
        int lane = tid & 31, wid = tid >> 5;
        if (lane == 0) { rsum[wid] = s; rsum2[wid] = s2; }
        __syncthreads();
        if (wid == 0) {
            float a  = (lane < 16) ? rsum[lane]  : 0.0f;
            float a2 = (lane < 16) ? rsum2[lane] : 0.0f;
#pragma unroll
            for (int d = 8; d; d >>= 1) {
                a  += __shfl_xor_sync(0xFFFFFFFFu, a, d);
                a2 += __shfl_xor_sync(0xFFFFFFFFu, a2, d);
            }
            if (lane == 0) { bcast[0] = a; bcast[1] = a2; }
        }
        __syncthreads();
        float m   = bcast[0] * (1.0f / 512.0f);
        float var = bcast[1] * (1.0f / 512.0f) - m * m;
        z = (acc - m) * rsqrtf(var + 1e-5f) * gamma[r] + beta[r];
    }
    if (mode >= 1) z = z * (1.0f / (1.0f + __expf(-z)));
    if (outTransposed) out[r * BATCH + tid] = z;
    else               out[(size_t)tid * outDim + r] = z;
}

// ---------------------------------------------------------------------------
// kernel_launch: kernel launches only (graph-capturable)
// ---------------------------------------------------------------------------
extern "C" void kernel_launch(void* const* d_in, const int* in_sizes, int n_in,
                              void* d_out, int out_size) {
    const float* x    = (const float*)d_in[0];
    const int*   idx1 = (const int*)  d_in[1];
    const float* val1 = (const float*)d_in[2];
    const float* b1   = (const float*)d_in[3];
    const int*   idx2 = (const int*)  d_in[4];
    const float* val2 = (const float*)d_in[5];
    const float* b2   = (const float*)d_in[6];
    const int*   idx3 = (const int*)  d_in[7];
    const float* val3 = (const float*)d_in[8];
    const float* b3   = (const float*)d_in[9];
    const int*   idx4 = (const int*)  d_in[10];
    const float* val4 = (const float*)d_in[11];
    const float* b4   = (const float*)d_in[12];
    const int*   idx5 = (const int*)  d_in[13];
    const float* val5 = (const float*)d_in[14];
    const float* b5   = (const float*)d_in[15];
    const float* g1   = (const float*)d_in[16];
    const float* be1  = (const float*)d_in[17];
    const float* g2   = (const float*)d_in[18];
    const float* be2  = (const float*)d_in[19];
    const float* g3   = (const float*)d_in[20];
    const float* be3  = (const float*)d_in[21];

    int nnz1 = in_sizes[1]  / 2;
    int nnz2 = in_sizes[4]  / 2;
    int nnz3 = in_sizes[7]  / 2;
    int nnz4 = in_sizes[10] / 2;
    int nnz5 = in_sizes[13] / 2;

    float *h1, *h2, *h3, *h4;
    cudaGetSymbolAddress((void**)&h1, g_h1);
    cudaGetSymbolAddress((void**)&h2, g_h2);
    cudaGetSymbolAddress((void**)&h3, g_h3);
    cudaGetSymbolAddress((void**)&h4, g_h4);

    cudaFuncSetAttribute(spmm1_kernel,
                         cudaFuncAttributeMaxDynamicSharedMemorySize, SPMM1_SMEM);

    // 0) zero bin counters
    zero_cnt_kernel<<<(BINS1 + 255) / 256, 256>>>();

    // 1) scatter pairs into fixed-capacity bins (no hist / no scan)
    scatter1_kernel<<<(nnz1 + 255) / 256, 256>>>(idx1, val1, nnz1);
    {
        int mx = max(max(nnz2, nnz3), max(nnz4, nnz5));
        scatter_small_kernel<<<dim3((mx + 255) / 256, 4), 256>>>(
            idx2, val2, nnz2, idx3, val3, nnz3,
            idx4, val4, nnz4, idx5, val5, nnz5);
    }
    pad_bins_kernel<<<(BINS1 + 255) / 256, 256>>>();

    // 2) layer 1: SMEM-tiled SpMM -> partials -> reduce + BN + SiLU
    spmm1_kernel<<<dim3(NCB, NBB), 1024, SPMM1_SMEM>>>(x);
    bn_silu_kernel<<<H1, 512>>>(b1, g1, be1, h1);

    // 3) layers 2..5
    spmm_kernel<<<H1, 512>>>(h1, b2, (const float*)0, (const float*)0, h2, SB2, 1, H1, 1);
    spmm_kernel<<<H2, 512>>>(h2, b3, g2, be2, h3, SB3, 2, H2, 1);
    spmm_kernel<<<H3, 512>>>(h3, b4, g3, be3, h4, SB4, 2, H3, 1);
    spmm_kernel<<<H3, 512>>>(h4, b5, (const float*)0, (const float*)0,
                             (float*)d_out, SB5, 0, H3, 0);
}

// round 17
// speedup vs baseline: 2.3117x; 1.3889x over previous
#include <cuda_runtime.h>
#include <cuda_fp16.h>
#include <cstdint>

// ---------------------------------------------------------------------------
// Problem constants
// ---------------------------------------------------------------------------
#define D_IN   120000
#define BATCH  512
#define H1     600
#define H2     300
#define H3     200

// ---------------------------------------------------------------------------
// Layer-1 SMEM-tiled SpMM geometry (fp16 x-tile)
// ---------------------------------------------------------------------------
#define COLB   384                  // columns per block
#define NCB    313                  // ceil(120000/384); last block has 192 cols
#define BB     256                  // batch lanes per CTA (fp16 doubles it)
#define NBB    (BATCH / BB)         // 2
// tile: COLB rows x 128 half2 words (=256 half) = 196608 B
#define XTILE_WORDS (COLB * 128)
#define XTILE_BYTES (XTILE_WORDS * 4)
#define SPMM1_SMEM  (XTILE_BYTES + H1 * 4)      // + per-row count cache

// Fixed-capacity bins (no histogram / no scan needed).
// Layer-1 bin = (colblock, row): Poisson(38.4) -> CAP1=128 is >9 sigma safe.
#define BINS1  (NCB * H1)           // 187800
#define CAP1   128                  // slots per layer-1 bin (1KB-aligned)
// Small layers keyed by row: Poisson(<=60) -> CAP_S=256 is enormous margin.
#define SB2    0
#define SB3    (SB2 + H1)           // 600
#define SB4    (SB3 + H2)           // 900
#define SB5    (SB4 + H3)           // 1100
#define BINS_S (SB5 + H3)           // 1300
#define CAP_S  256

// Swizzle (word granularity; a word = half2 = batches (2*b2, 2*b2+1)):
//   word(cl, b2) = cl*128 + (b2 ^ PERM(cl)),  PERM(cl) = ((cl>>2)&31)<<2
//  - gather (fixed cl, b2 = 4*lane..4*lane+3): 16B chunk = lane ^ ((cl>>2)&31),
//    bijection over lanes -> conflict-free LDS.128 (16B-aligned, PERM%4==0)
//  - store  (fixed b2, cl = 4*cq+j, cq consecutive): 8 banks -> 4-way max
#define PERM(cl) ((((cl) >> 2) & 31) << 2)

// ---------------------------------------------------------------------------
// Static device scratch (allocation-free rule).  +8 pad slots: the inner-loop
// prefetch may read up to 1 float4 (2 pairs) past the last bin.
// ---------------------------------------------------------------------------
__device__ float2 g_pairs1[(size_t)BINS1 * CAP1 + 8];   // 192.3 MB
__device__ float2 g_pairsS[(size_t)BINS_S * CAP_S];     // 2.7 MB
__device__ int    g_cnt1[BINS1];
__device__ int    g_cntS[BINS_S];
__device__ float  g_part[(size_t)NCB * H1 * BATCH];     // 384.6 MB [cb][r][b]
__device__ float  g_h1[H1 * BATCH];
__device__ float  g_h2[H1 * BATCH];
__device__ float  g_h3[H2 * BATCH];
__device__ float  g_h4[H3 * BATCH];

// ---------------------------------------------------------------------------
// 0) zero bin counters
// ---------------------------------------------------------------------------
__global__ void zero_cnt_kernel() {
    int i = blockIdx.x * blockDim.x + threadIdx.x;
    if (i < BINS1) g_cnt1[i] = 0;
    if (i < BINS_S) g_cntS[i] = 0;
}

// ---------------------------------------------------------------------------
// 1) scatter layer-1 pairs into capacity bins.
//    pairs.x = precomputed swizzled word offset cl*128 + PERM(cl)
// ---------------------------------------------------------------------------
__global__ void scatter1_kernel(const int* __restrict__ idx,
                                const float* __restrict__ val, int nnz) {
    int j = blockIdx.x * blockDim.x + threadIdx.x;
    if (j >= nnz) return;
    int r = idx[j];
    int c = idx[nnz + j];
    int cb = c / COLB;
    int cl = c - cb * COLB;
    int key = cb * H1 + r;
    int fill = atomicAdd(&g_cnt1[key], 1);
    if (fill >= CAP1 - 2) return;            // statistically impossible; guard
    int px = cl * 128 + PERM(cl);
    g_pairs1[(size_t)key * CAP1 + fill] = make_float2(__int_as_float(px), val[j]);
}

// ---------------------------------------------------------------------------
// 1b) pad bins: clamp count and zero the pair after the last one when cnt is
//     odd, so the SpMM loop runs whole float4s with no tail branch.
// ---------------------------------------------------------------------------
__global__ void pad_bins_kernel() {
    int key = blockIdx.x * blockDim.x + threadIdx.x;
    if (key >= BINS1) return;
    int cnt = g_cnt1[key];
    if (cnt > CAP1 - 2) { cnt = CAP1 - 2; g_cnt1[key] = cnt; }
    if (cnt & 1)
        g_pairs1[(size_t)key * CAP1 + cnt] = make_float2(0.f, 0.f);
}

// ---------------------------------------------------------------------------
// 2) scatter small-layer pairs (layers 2..5 fused via blockIdx.y)
// ---------------------------------------------------------------------------
__global__ void scatter_small_kernel(
    const int* __restrict__ i2, const float* __restrict__ v2, int n2,
    const int* __restrict__ i3, const float* __restrict__ v3, int n3,
    const int* __restrict__ i4, const float* __restrict__ v4, int n4,
    const int* __restrict__ i5, const float* __restrict__ v5, int n5)
{
    const int* p; const float* v; int n, sb;
    switch (blockIdx.y) {
        case 0: p = i2; v = v2; n = n2; sb = SB2; break;
        case 1: p = i3; v = v3; n = n3; sb = SB3; break;
        case 2: p = i4; v = v4; n = n4; sb = SB4; break;
        default: p = i5; v = v5; n = n5; sb = SB5; break;
    }
    int j = blockIdx.x * blockDim.x + threadIdx.x;
    if (j >= n) return;
    int key = sb + p[j];
    int fill = atomicAdd(&g_cntS[key], 1);
    if (fill >= CAP_S) return;
    g_pairsS[(size_t)key * CAP_S + fill] =
        make_float2(__int_as_float(p[n + j]), v[j]);
}

// ---------------------------------------------------------------------------
// 3) Layer-1 SpMM: CTA = (col-block, batch-block of 256), 1024 thr = 32 warps.
//    x tile in SMEM as half2 (swizzled); accumulation in fp32. Pairs streamed
//    as float4 (2 pairs) with branch-free 2-deep prefetch; lane owns batches
//    8*lane..8*lane+7; warp w sweeps rows w, w+32, ...
// ---------------------------------------------------------------------------
__global__ void __launch_bounds__(1024, 1) spmm1_kernel(const float* __restrict__ x) {
    extern __shared__ char smem[];
    uint32_t* xsw = (uint32_t*)smem;            // half2 words
    int* sCnt = (int*)(smem + XTILE_BYTES);
    const int cb  = blockIdx.x;
    const int bbk = blockIdx.y;
    const int c0 = cb * COLB;
    const int ncols = min(COLB, D_IN - c0);
    const int tid = threadIdx.x;

    // per-row pair counts for this colblock -> SMEM (600 ints)
    for (int i = tid; i < H1; i += 1024)
        sCnt[i] = g_cnt1[cb * H1 + i];

    // x tile: convert fp32 -> half2 words [cl][b2], swizzled.
    // unit = (cq, b2): 4 words for cl = 4cq..4cq+3 built from batch rows
    // (2*b2, 2*b2+1); global reads coalesced float4.
    {
        const float* xb = x + (size_t)(bbk * BB) * D_IN + c0;
        const int nq = ncols >> 2;              // 4-column units per row
        const int total = nq * (BB / 2);        // x 128 b2 values
        for (int idx = tid; idx < total; idx += 1024) {
            int cq = idx % nq;
            int b2 = idx / nq;
            const float* r0 = xb + (size_t)(2 * b2) * D_IN + 4 * cq;
            float4 f0 = __ldcs((const float4*)r0);
            float4 f1 = __ldcs((const float4*)(r0 + D_IN));
            int base = (4 * cq) * 128 + (b2 ^ ((cq & 31) << 2));
            __half2 h0 = __floats2half2_rn(f0.x, f1.x);
            __half2 h1 = __floats2half2_rn(f0.y, f1.y);
            __half2 h2 = __floats2half2_rn(f0.z, f1.z);
            __half2 h3 = __floats2half2_rn(f0.w, f1.w);
            xsw[base + 0 * 128] = *(uint32_t*)&h0;
            xsw[base + 1 * 128] = *(uint32_t*)&h1;
            xsw[base + 2 * 128] = *(uint32_t*)&h2;
            xsw[base + 3 * 128] = *(uint32_t*)&h3;
        }
    }
    __syncthreads();

    const int w    = tid >> 5;          // warp 0..31: rows w, w+32, ...
    const int lane = tid & 31;          // batches 8*lane .. 8*lane+7
    const uint32_t l4 = (uint32_t)lane << 2;   // word-offset XOR

    for (int r = w; r < H1; r += 32) {
        const int cnt = sCnt[r];        // bin padded: odd slot holds val=0
        const int nQ  = (cnt + 1) >> 1; // whole float4 iterations, no tail
        const float4* pq = (const float4*)(g_pairs1 + (size_t)(cb * H1 + r) * CAP1);

        float a0=0.f,a1=0.f,a2=0.f,a3=0.f,a4=0.f,a5=0.f,a6=0.f,a7=0.f;

        if (nQ > 0) {
            float4 q  = __ldg(pq);
            float4 qn = __ldg(pq + 1);
            for (int i = 0; i < nQ; ++i) {
                float4 cur = q;
                q = qn;
                qn = __ldg(pq + i + 2);     // overshoot lands in pad/next bin
                {
                    const uint4 hw = *(const uint4*)(xsw + (__float_as_uint(cur.x) ^ l4));
                    const float wv = cur.y;
                    float2 v0 = __half22float2(*(const __half2*)&hw.x);
                    float2 v1 = __half22float2(*(const __half2*)&hw.y);
                    float2 v2 = __half22float2(*(const __half2*)&hw.z);
                    float2 v3 = __half22float2(*(const __half2*)&hw.w);
                    a0 += wv * v0.x; a1 += wv * v0.y;
                    a2 += wv * v1.x; a3 += wv * v1.y;
                    a4 += wv * v2.x; a5 += wv * v2.y;
                    a6 += wv * v3.x; a7 += wv * v3.y;
                }
                {
                    const uint4 hw = *(const uint4*)(xsw + (__float_as_uint(cur.z) ^ l4));
                    const float wv = cur.w;
                    float2 v0 = __half22float2(*(const __half2*)&hw.x);
                    float2 v1 = __half22float2(*(const __half2*)&hw.y);
                    float2 v2 = __half22float2(*(const __half2*)&hw.z);
                    float2 v3 = __half22float2(*(const __half2*)&hw.w);
                    a0 += wv * v0.x; a1 += wv * v0.y;
                    a2 += wv * v1.x; a3 += wv * v1.y;
                    a4 += wv * v2.x; a5 += wv * v2.y;
                    a6 += wv * v3.x; a7 += wv * v3.y;
                }
            }
        }
        float* dst = g_part + (size_t)(cb * H1 + r) * BATCH + bbk * BB + 8 * lane;
        __stcs((float4*)dst,       make_float4(a0, a1, a2, a3));
        __stcs((float4*)(dst + 4), make_float4(a4, a5, a6, a7));
    }
}

// ---------------------------------------------------------------------------
// 4) reduce colblock partials + bias + BN + SiLU -> g_h1 [r][512]
// ---------------------------------------------------------------------------
__global__ void __launch_bounds__(512) bn_silu_kernel(
    const float* __restrict__ bias, const float* __restrict__ gamma,
    const float* __restrict__ beta, float* __restrict__ out)
{
    int r = blockIdx.x, tid = threadIdx.x;
    const float* p = g_part + (size_t)r * BATCH + tid;
    const size_t stride = (size_t)H1 * BATCH;
    float a0 = 0.f, a1 = 0.f, a2 = 0.f, a3 = 0.f;
    int cbi = 0;
    for (; cbi + 4 <= NCB; cbi += 4) {
        a0 += __ldcs(p + (size_t)(cbi + 0) * stride);
        a1 += __ldcs(p + (size_t)(cbi + 1) * stride);
        a2 += __ldcs(p + (size_t)(cbi + 2) * stride);
        a3 += __ldcs(p + (size_t)(cbi + 3) * stride);
    }
    for (; cbi < NCB; ++cbi) a0 += __ldcs(p + (size_t)cbi * stride);
    float acc = (a0 + a1) + (a2 + a3) + bias[r];

    __shared__ float rsum[16], rsum2[16], bcast[2];
    float s = acc, s2 = acc * acc;
#pragma unroll
    for (int d = 16; d; d >>= 1) {
        s  += __shfl_xor_sync(0xFFFFFFFFu, s, d);
        s2 += __shfl_xor_sync(0xFFFFFFFFu, s2, d);
    }
    int lane = tid & 31, wid = tid >> 5;
    if (lane == 0) { rsum[wid] = s; rsum2[wid] = s2; }
    __syncthreads();
    if (wid == 0) {
        float a   = (lane < 16) ? rsum[lane]  : 0.0f;
        float a2w = (lane < 16) ? rsum2[lane] : 0.0f;
#pragma unroll
        for (int d = 8; d; d >>= 1) {
            a   += __shfl_xor_sync(0xFFFFFFFFu, a, d);
            a2w += __shfl_xor_sync(0xFFFFFFFFu, a2w, d);
        }
        if (lane == 0) { bcast[0] = a; bcast[1] = a2w; }
    }
    __syncthreads();
    float m   = bcast[0] * (1.0f / 512.0f);
    float var = bcast[1] * (1.0f / 512.0f) - m * m;
    float z = (acc - m) * rsqrtf(var + 1e-5f) * gamma[r] + beta[r];
    z = z * (1.0f / (1.0f + __expf(-z)));
    out[r * BATCH + tid] = z;
}

// ---------------------------------------------------------------------------
// 5) small sparse layers 2..5;  mode: 0 = raw, 1 = silu, 2 = bn + silu
//    cnt <= CAP_S = 256 < 512, so a single staging pass suffices.
// ---------------------------------------------------------------------------
__global__ void __launch_bounds__(512) spmm_kernel(
    const float* __restrict__ inT, const float* __restrict__ bias,
    const float* __restrict__ gamma, const float* __restrict__ beta,
    float* __restrict__ out, int sb, int mode, int outDim, int outTransposed)
{
    __shared__ float2 sh[CAP_S];
    int r = blockIdx.x, tid = threadIdx.x;
    const int cnt = g_cntS[sb + r];
    const float2* binp = g_pairsS + (size_t)(sb + r) * CAP_S;

    if (tid < cnt) sh[tid] = binp[tid];
    __syncthreads();

    float acc = 0.0f;
    int k = 0;
    for (; k + 4 <= cnt; k += 4) {
        float2 p0 = sh[k], p1 = sh[k+1], p2 = sh[k+2], p3 = sh[k+3];
        acc += p0.y * inT[__float_as_int(p0.x) * BATCH + tid];
        acc += p1.y * inT[__float_as_int(p1.x) * BATCH + tid];
        acc += p2.y * inT[__float_as_int(p2.x) * BATCH + tid];
        acc += p3.y * inT[__float_as_int(p3.x) * BATCH + tid];
    }
    for (; k < cnt; k++) {
        float2 p = sh[k];
        acc += p.y * inT[__float_as_int(p.x) * BATCH + tid];
    }
    acc += bias[r];

    float z = acc;
    if (mode >= 2) {
        __shared__ float rsum[16], rsum2[16], bcast[2];
        float s = acc, s2 = acc * acc;
#pragma unroll
        for (int d = 16; d; d >>= 1) {
            s  += __shfl_xor_sync(0xFFFFFFFFu, s, d);
            s2 += __shfl_xor_sync(0xFFFFFFFFu, s2, d);
        }
        int lane = tid & 31, wid = tid >> 5;
        if (lane == 0) { rsum[wid] = s; rsum2[wid] = s2; }
        __syncthreads();
        if (wid == 0) {
            float a  = (lane < 16) ? rsum[lane]  : 0.0f;
            float a2 = (lane < 16) ? rsum2[lane] : 0.0f;
#pragma unroll
            for (int d = 8; d; d >>= 1) {
                a  += __shfl_xor_sync(0xFFFFFFFFu, a, d);
                a2 += __shfl_xor_sync(0xFFFFFFFFu, a2, d);
            }
            if (lane == 0) { bcast[0] = a; bcast[1] = a2; }
        }
        __syncthreads();
        float m   = bcast[0] * (1.0f / 512.0f);
        float var = bcast[1] * (1.0f / 512.0f) - m * m;
        z = (acc - m) * rsqrtf(var + 1e-5f) * gamma[r] + beta[r];
    }
    if (mode >= 1) z = z * (1.0f / (1.0f + __expf(-z)));
    if (outTransposed) out[r * BATCH + tid] = z;
    else               out[(size_t)tid * outDim + r] = z;
}

// ---------------------------------------------------------------------------
// kernel_launch: kernel launches only (graph-capturable)
// ---------------------------------------------------------------------------
extern "C" void kernel_launch(void* const* d_in, const int* in_sizes, int n_in,
                              void* d_out, int out_size) {
    const float* x    = (const float*)d_in[0];
    const int*   idx1 = (const int*)  d_in[1];
    const float* val1 = (const float*)d_in[2];
    const float* b1   = (const float*)d_in[3];
    const int*   idx2 = (const int*)  d_in[4];
    const float* val2 = (const float*)d_in[5];
    const float* b2   = (const float*)d_in[6];
    const int*   idx3 = (const int*)  d_in[7];
    const float* val3 = (const float*)d_in[8];
    const float* b3   = (const float*)d_in[9];
    const int*   idx4 = (const int*)  d_in[10];
    const float* val4 = (const float*)d_in[11];
    const float* b4   = (const float*)d_in[12];
    const int*   idx5 = (const int*)  d_in[13];
    const float* val5 = (const float*)d_in[14];
    const float* b5   = (const float*)d_in[15];
    const float* g1   = (const float*)d_in[16];
    const float* be1  = (const float*)d_in[17];
    const float* g2   = (const float*)d_in[18];
    const float* be2  = (const float*)d_in[19];
    const float* g3   = (const float*)d_in[20];
    const float* be3  = (const float*)d_in[21];

    int nnz1 = in_sizes[1]  / 2;
    int nnz2 = in_sizes[4]  / 2;
    int nnz3 = in_sizes[7]  / 2;
    int nnz4 = in_sizes[10] / 2;
    int nnz5 = in_sizes[13] / 2;

    float *h1, *h2, *h3, *h4;
    cudaGetSymbolAddress((void**)&h1, g_h1);
    cudaGetSymbolAddress((void**)&h2, g_h2);
    cudaGetSymbolAddress((void**)&h3, g_h3);
    cudaGetSymbolAddress((void**)&h4, g_h4);

    cudaFuncSetAttribute(spmm1_kernel,
                         cudaFuncAttributeMaxDynamicSharedMemorySize, SPMM1_SMEM);

    // 0) zero bin counters
    zero_cnt_kernel<<<(BINS1 + 255) / 256, 256>>>();

    // 1) scatter pairs into fixed-capacity bins (no hist / no scan)
    scatter1_kernel<<<(nnz1 + 255) / 256, 256>>>(idx1, val1, nnz1);
    {
        int mx = max(max(nnz2, nnz3), max(nnz4, nnz5));
        scatter_small_kernel<<<dim3((mx + 255) / 256, 4), 256>>>(
            idx2, val2, nnz2, idx3, val3, nnz3,
            idx4, val4, nnz4, idx5, val5, nnz5);
    }
    pad_bins_kernel<<<(BINS1 + 255) / 256, 256>>>();

    // 2) layer 1: SMEM-tiled SpMM (fp16 tile) -> partials -> BN + SiLU
    spmm1_kernel<<<dim3(NCB, NBB), 1024, SPMM1_SMEM>>>(x);
    bn_silu_kernel<<<H1, 512>>>(b1, g1, be1, h1);

    // 3) layers 2..5
    spmm_kernel<<<H1, 512>>>(h1, b2, (const float*)0, (const float*)0, h2, SB2, 1, H1, 1);
    spmm_kernel<<<H2, 512>>>(h2, b3, g2, be2, h3, SB3, 2, H2, 1);
    spmm_kernel<<<H3, 512>>>(h3, b4, g3, be3, h4, SB4, 2, H3, 1);
    spmm_kernel<<<H3, 512>>>(h4, b5, (const float*)0, (const float*)0,
                             (float*)d_out, SB5, 0, H3, 0);
}